// round 15
// baseline (speedup 1.0000x reference)
#include <cuda_runtime.h>
#include <cuda_bf16.h>
#include <cuda_fp16.h>
#include <cstdint>
#include <math.h>

// ---------------------------------------------------------------------------
// Problem constants
// ---------------------------------------------------------------------------
#define M_ROWS   32768
#define C_DIM    128
#define L_DIM    4096
#define B_DIM    8
#define HID      512
#define QKV_N    384
#define ZC       512

// ---------------------------------------------------------------------------
// Scratch buffers.  fp16 tensors stored as packed half2 words (uint32).
// ---------------------------------------------------------------------------
__device__ __align__(16) float    g_xf  [M_ROWS * C_DIM];
__device__ __align__(16) float    g_xf2 [M_ROWS * C_DIM];
__device__ __align__(16) uint32_t g_h1h [M_ROWS * (C_DIM/2)];
__device__ __align__(16) uint32_t g_qkvh[M_ROWS * (QKV_N/2)];
__device__ __align__(16) uint32_t g_atth[M_ROWS * (C_DIM/2)];
__device__ __align__(16) uint32_t g_h2h [M_ROWS * (C_DIM/2)];
__device__ __align__(16) uint32_t g_midh[M_ROWS * (HID/2)];
__device__ __align__(16) float    g_z1  [B_DIM * C_DIM];
__device__ __align__(16) float    g_z2  [B_DIM * C_DIM];
// fp16 weights (packed half2 along K)
__device__ __align__(16) uint32_t g_wqkvh[QKV_N * (C_DIM/2)];
__device__ __align__(16) uint32_t g_wprojh[C_DIM * (C_DIM/2)];
__device__ __align__(16) uint32_t g_w1h  [HID * (C_DIM/2)];
__device__ __align__(16) uint32_t g_w2h  [C_DIM * (HID/2)];

#define SOFTMAX_SC 0.36067376022224085f   // 0.25 * log2(e)
#define INV_SC     2.7725887222397811f    // 1 / SOFTMAX_SC = 4 ln 2

// ---------------------------------------------------------------------------
// helpers
// ---------------------------------------------------------------------------
__device__ __forceinline__ uint32_t pack_h2(float lo, float hi) {
    uint32_t u;
    asm("cvt.rn.f16x2.f32 %0, %1, %2;" : "=r"(u) : "f"(hi), "f"(lo));
    return u;
}
__device__ __forceinline__ uint32_t ex2_h2(uint32_t h2) {
    uint32_t r;
    asm("ex2.approx.f16x2 %0, %1;" : "=r"(r) : "r"(h2));
    return r;
}
__device__ __forceinline__ float fast_ex2(float x) {
    float y;
    asm("ex2.approx.ftz.f32 %0, %1;" : "=f"(y) : "f"(x));
    return y;
}
__device__ __forceinline__ float gelu_f(float v) {
    return 0.5f * v * (1.f + erff(v * 0.70710678118654752f));
}
__device__ __forceinline__ void mma16n8k16(float* d, const uint32_t* a,
                                           const uint32_t* b) {
    asm("mma.sync.aligned.m16n8k16.row.col.f32.f16.f16.f32 "
        "{%0,%1,%2,%3}, {%4,%5,%6,%7}, {%8,%9}, {%0,%1,%2,%3};"
        : "+f"(d[0]), "+f"(d[1]), "+f"(d[2]), "+f"(d[3])
        : "r"(a[0]), "r"(a[1]), "r"(a[2]), "r"(a[3]), "r"(b[0]), "r"(b[1]));
}

// ---------------------------------------------------------------------------
// prep: z projections (blocks 0-7) + weight fp16 conversion (blocks 8-55)
// ---------------------------------------------------------------------------
__global__ void prep_kernel(const float* __restrict__ z,
                            const float* __restrict__ Wz1,
                            const float* __restrict__ Wz2,
                            const float* __restrict__ Wqkv,
                            const float* __restrict__ Wproj,
                            const float* __restrict__ W1,
                            const float* __restrict__ W2) {
    if (blockIdx.x < 8) {
        int o = blockIdx.x * 256 + threadIdx.x;
        int which = o >> 10;
        int b = (o >> 7) & 7;
        int c = o & 127;
        const float* W = (which ? Wz2 : Wz1) + c * ZC;
        const float* zb = z + b * ZC;
        float s = 0.f;
        #pragma unroll 8
        for (int k = 0; k < ZC; k++) s += zb[k] * W[k];
        (which ? g_z2 : g_z1)[b * C_DIM + c] = s;
        return;
    }
    int idx = (blockIdx.x - 8) * 2048 + threadIdx.x * 8;
    const float* src; uint32_t* dst; int base;
    if (idx < 24576)      { src = Wqkv;  dst = g_wqkvh;  base = idx; }
    else if (idx < 32768) { src = Wproj; dst = g_wprojh; base = idx - 24576; }
    else if (idx < 65536) { src = W1;    dst = g_w1h;    base = idx - 32768; }
    else                  { src = W2;    dst = g_w2h;    base = idx - 65536; }
    const float* s = src + (size_t)base * 2;
    uint32_t w[8];
    #pragma unroll
    for (int i = 0; i < 4; i++) {
        float4 v = ((const float4*)s)[i];
        w[2*i]   = pack_h2(v.x, v.y);
        w[2*i+1] = pack_h2(v.z, v.w);
    }
    uint4 o0 = {w[0], w[1], w[2], w[3]};
    uint4 o1 = {w[4], w[5], w[6], w[7]};
    *(uint4*)(dst + base)     = o0;
    *(uint4*)(dst + base + 4) = o1;
}

// ---------------------------------------------------------------------------
// Transpose x -> xf (fp32) and h1 = LN(xf)+z1 packed fp16.
// ---------------------------------------------------------------------------
__global__ void __launch_bounds__(256) ln1_kernel(const float* __restrict__ x,
                                                  const float* __restrict__ gamma,
                                                  const float* __restrict__ beta) {
    __shared__ float sm[128][33];
    int b  = blockIdx.y;
    int l0 = blockIdx.x * 32;
    int tid = threadIdx.x;
    const float* xb = x + (size_t)b * C_DIM * L_DIM;
    #pragma unroll
    for (int r = 0; r < 16; r++) {
        int c = r * 8 + (tid >> 5);
        int j = tid & 31;
        sm[c][j] = xb[(size_t)c * L_DIM + l0 + j];
    }
    __syncthreads();
    int warp = tid >> 5, lane = tid & 31;
    #pragma unroll
    for (int rr = 0; rr < 4; rr++) {
        int j = warp + rr * 8;
        float v[4];
        v[0] = sm[2 * lane][j];
        v[1] = sm[2 * lane + 1][j];
        v[2] = sm[64 + 2 * lane][j];
        v[3] = sm[65 + 2 * lane][j];
        float s = v[0] + v[1] + v[2] + v[3];
        float s2 = v[0]*v[0] + v[1]*v[1] + v[2]*v[2] + v[3]*v[3];
        #pragma unroll
        for (int o = 16; o; o >>= 1) {
            s  += __shfl_xor_sync(0xffffffffu, s,  o);
            s2 += __shfl_xor_sync(0xffffffffu, s2, o);
        }
        float mu   = s  * (1.f / 128.f);
        float var  = s2 * (1.f / 128.f) - mu * mu;
        float rstd = rsqrtf(var + 1e-5f);
        int l = l0 + j;
        size_t row = (size_t)b * L_DIM + l;
        float* xfr = g_xf + row * C_DIM;
        *(float2*)(xfr + 2 * lane)      = make_float2(v[0], v[1]);
        *(float2*)(xfr + 64 + 2 * lane) = make_float2(v[2], v[3]);
        const float* z1b = g_z1 + b * C_DIM;
        float h[4];
        #pragma unroll
        for (int u = 0; u < 4; u++) {
            int c = (u < 2) ? (2 * lane + u) : (62 + 2 * lane + u);
            h[u] = (v[u] - mu) * rstd * gamma[c] + beta[c] + z1b[c];
        }
        uint32_t* hr = g_h1h + row * 64;
        hr[lane]      = pack_h2(h[0], h[1]);
        hr[32 + lane] = pack_h2(h[2], h[3]);
    }
}

// ---------------------------------------------------------------------------
// Lean tensor-core GEMM, BK=32, both operands fp16 words, [row][RS] smem.
// CH=0: C fp32 with optional res;  CH=1: C fp16 words, optional qscale.
// ---------------------------------------------------------------------------
#define RS 20

template<int CH>
__global__ void __launch_bounds__(256) gemm_h(
        const uint32_t* __restrict__ A, const uint32_t* __restrict__ Wh,
        const float* __restrict__ bias, const float* __restrict__ res,
        void* __restrict__ Cv, int M, int N, int K, int act, int qsc) {
    __shared__ uint32_t As[2][128 * RS];
    __shared__ uint32_t Bs[2][128 * RS];
    int tid  = threadIdx.x;
    int warp = tid >> 5, lane = tid & 31;
    int wm = warp >> 2;
    int wn = warp & 3;
    int t = lane & 3, g = lane >> 2;
    int m0 = blockIdx.y * 128, n0 = blockIdx.x * 128;
    int K2 = K >> 1;

    float acc[4][4][4];
    #pragma unroll
    for (int i = 0; i < 4; i++)
        #pragma unroll
        for (int j = 0; j < 4; j++)
            #pragma unroll
            for (int r = 0; r < 4; r++) acc[i][j][r] = 0.f;

    int arow = tid >> 1;
    int aoff = (tid & 1) << 3;
    uint4 pa[2], pb[2];
    {
        const uint32_t* ap = A  + (size_t)(m0 + arow) * K2 + aoff;
        const uint32_t* bp = Wh + (size_t)(n0 + arow) * K2 + aoff;
        pa[0] = *(const uint4*)ap;     pa[1] = *(const uint4*)(ap + 4);
        pb[0] = *(const uint4*)bp;     pb[1] = *(const uint4*)(bp + 4);
    }

    int slabs = K >> 5;
    for (int s = 0; s < slabs; s++) {
        uint32_t* Ab = As[s & 1];
        uint32_t* Bb = Bs[s & 1];
        {
            uint4* da = (uint4*)&Ab[arow * RS + aoff];
            da[0] = pa[0]; da[1] = pa[1];
            uint4* db = (uint4*)&Bb[arow * RS + aoff];
            db[0] = pb[0]; db[1] = pb[1];
        }
        __syncthreads();
        if (s + 1 < slabs) {
            const uint32_t* ap = A  + (size_t)(m0 + arow) * K2 + (s + 1) * 16 + aoff;
            const uint32_t* bp = Wh + (size_t)(n0 + arow) * K2 + (s + 1) * 16 + aoff;
            pa[0] = *(const uint4*)ap;  pa[1] = *(const uint4*)(ap + 4);
            pb[0] = *(const uint4*)bp;  pb[1] = *(const uint4*)(bp + 4);
        }
        #pragma unroll
        for (int ks = 0; ks < 2; ks++) {
            uint32_t af[4][4], bf[4][2];
            #pragma unroll
            for (int i = 0; i < 4; i++) {
                const uint32_t* p = Ab + (wm * 64 + i * 16 + g) * RS + ks * 8 + t;
                af[i][0] = p[0];
                af[i][1] = p[8 * RS];
                af[i][2] = p[4];
                af[i][3] = p[8 * RS + 4];
            }
            #pragma unroll
            for (int j = 0; j < 4; j++) {
                const uint32_t* p = Bb + (wn * 32 + j * 8 + g) * RS + ks * 8 + t;
                bf[j][0] = p[0];
                bf[j][1] = p[4];
            }
            #pragma unroll
            for (int i = 0; i < 4; i++)
                #pragma unroll
                for (int j = 0; j < 4; j++)
                    mma16n8k16(acc[i][j], af[i], bf[j]);
        }
        __syncthreads();
    }

    if (CH == 0) {
        float* C = (float*)Cv;
        #pragma unroll
        for (int i = 0; i < 4; i++) {
            int mr = m0 + wm * 64 + i * 16 + g;
            #pragma unroll
            for (int half = 0; half < 2; half++) {
                int m = mr + 8 * half;
                size_t ro = (size_t)m * N;
                #pragma unroll
                for (int j = 0; j < 4; j++) {
                    int n = n0 + wn * 32 + j * 8 + 2 * t;
                    float vx = acc[i][j][2 * half];
                    float vy = acc[i][j][2 * half + 1];
                    if (bias) { vx += bias[n]; vy += bias[n + 1]; }
                    if (res) {
                        float2 rv = *(const float2*)(res + ro + n);
                        vx += rv.x; vy += rv.y;
                    }
                    if (act) { vx = gelu_f(vx); vy = gelu_f(vy); }
                    *(float2*)(C + ro + n) = make_float2(vx, vy);
                }
            }
        }
    } else {
        uint32_t* Ch = (uint32_t*)Cv;
        int N2 = N >> 1;
        #pragma unroll
        for (int i = 0; i < 4; i++) {
            int mr = m0 + wm * 64 + i * 16 + g;
            #pragma unroll
            for (int half = 0; half < 2; half++) {
                int m = mr + 8 * half;
                size_t ro = (size_t)m * N2;
                #pragma unroll
                for (int j = 0; j < 4; j++) {
                    int n = n0 + wn * 32 + j * 8 + 2 * t;
                    float vx = acc[i][j][2 * half];
                    float vy = acc[i][j][2 * half + 1];
                    if (bias) { vx += bias[n]; vy += bias[n + 1]; }
                    if (act) { vx = gelu_f(vx); vy = gelu_f(vy); }
                    if (qsc && n < 128) { vx *= SOFTMAX_SC; vy *= SOFTMAX_SC; }
                    Ch[ro + (n >> 1)] = pack_h2(vx, vy);
                }
            }
        }
    }
}

// ---------------------------------------------------------------------------
// mlp2 GEMM with fused output transpose (reused GEMM smem, no extra shared).
// ---------------------------------------------------------------------------
__global__ void __launch_bounds__(256) gemm_trans_kernel(
        const uint32_t* __restrict__ A, const uint32_t* __restrict__ Wh,
        const float* __restrict__ bias, const float* __restrict__ res,
        float* __restrict__ Cout, int M, int K) {
    __shared__ __align__(16) union {
        uint32_t buf[4][128 * RS];
        float    ts[64 * 132];
    } smu;
    const int N = 128;
    int tid  = threadIdx.x;
    int warp = tid >> 5, lane = tid & 31;
    int wm = warp >> 2;
    int wn = warp & 3;
    int t = lane & 3, g = lane >> 2;
    int m0 = blockIdx.y * 128;
    int K2 = K >> 1;

    float acc[4][4][4];
    #pragma unroll
    for (int i = 0; i < 4; i++)
        #pragma unroll
        for (int j = 0; j < 4; j++)
            #pragma unroll
            for (int r = 0; r < 4; r++) acc[i][j][r] = 0.f;

    int arow = tid >> 1;
    int aoff = (tid & 1) << 3;
    uint4 pa[2], pb[2];
    {
        const uint32_t* ap = A  + (size_t)(m0 + arow) * K2 + aoff;
        const uint32_t* bp = Wh + (size_t)arow * K2 + aoff;
        pa[0] = *(const uint4*)ap;     pa[1] = *(const uint4*)(ap + 4);
        pb[0] = *(const uint4*)bp;     pb[1] = *(const uint4*)(bp + 4);
    }

    int slabs = K >> 5;
    for (int s = 0; s < slabs; s++) {
        uint32_t* Ab = smu.buf[s & 1];
        uint32_t* Bb = smu.buf[2 + (s & 1)];
        {
            uint4* da = (uint4*)&Ab[arow * RS + aoff];
            da[0] = pa[0]; da[1] = pa[1];
            uint4* db = (uint4*)&Bb[arow * RS + aoff];
            db[0] = pb[0]; db[1] = pb[1];
        }
        __syncthreads();
        if (s + 1 < slabs) {
            const uint32_t* ap = A  + (size_t)(m0 + arow) * K2 + (s + 1) * 16 + aoff;
            const uint32_t* bp = Wh + (size_t)arow * K2 + (s + 1) * 16 + aoff;
            pa[0] = *(const uint4*)ap;  pa[1] = *(const uint4*)(ap + 4);
            pb[0] = *(const uint4*)bp;  pb[1] = *(const uint4*)(bp + 4);
        }
        #pragma unroll
        for (int ks = 0; ks < 2; ks++) {
            uint32_t af[4][4], bf[4][2];
            #pragma unroll
            for (int i = 0; i < 4; i++) {
                const uint32_t* p = Ab + (wm * 64 + i * 16 + g) * RS + ks * 8 + t;
                af[i][0] = p[0];
                af[i][1] = p[8 * RS];
                af[i][2] = p[4];
                af[i][3] = p[8 * RS + 4];
            }
            #pragma unroll
            for (int j = 0; j < 4; j++) {
                const uint32_t* p = Bb + (wn * 32 + j * 8 + g) * RS + ks * 8 + t;
                bf[j][0] = p[0];
                bf[j][1] = p[4];
            }
            #pragma unroll
            for (int i = 0; i < 4; i++)
                #pragma unroll
                for (int j = 0; j < 4; j++)
                    mma16n8k16(acc[i][j], af[i], bf[j]);
        }
        __syncthreads();
    }

    int b  = m0 >> 12;
    int l0 = m0 & (L_DIM - 1);
    #pragma unroll
    for (int cc = 0; cc < 2; cc++) {
        if ((wn >> 1) == cc) {
            #pragma unroll
            for (int i = 0; i < 4; i++) {
                #pragma unroll
                for (int half = 0; half < 2; half++) {
                    int ml = wm * 64 + i * 16 + g + 8 * half;
                    size_t ro = (size_t)(m0 + ml) * N;
                    #pragma unroll
                    for (int j = 0; j < 4; j++) {
                        int n = wn * 32 + j * 8 + 2 * t;
                        float vx = acc[i][j][2 * half]     + bias[n];
                        float vy = acc[i][j][2 * half + 1] + bias[n + 1];
                        float2 rv = *(const float2*)(res + ro + n);
                        vx += rv.x; vy += rv.y;
                        int nn = n - cc * 64;
                        smu.ts[nn * 132 + ml]       = vx;
                        smu.ts[(nn + 1) * 132 + ml] = vy;
                    }
                }
            }
        }
        __syncthreads();
        #pragma unroll
        for (int it = 0; it < 8; it++) {
            int cl = warp * 8 + it;
            int c  = cc * 64 + cl;
            float4 v = *(const float4*)&smu.ts[cl * 132 + lane * 4];
            *(float4*)(Cout + ((size_t)b * C_DIM + c) * L_DIM + l0 + lane * 4) = v;
        }
        if (cc == 0) __syncthreads();
    }
}

// ---------------------------------------------------------------------------
// proj GEMM with fused LN2 (BK=32, fp16 weights).  N == 128, gridDim.x == 1.
// ---------------------------------------------------------------------------
__global__ void __launch_bounds__(256) gemm_ln_kernel(
        const uint32_t* __restrict__ A, const uint32_t* __restrict__ Wh,
        const float* __restrict__ bias, const float* __restrict__ res,
        float* __restrict__ C, uint32_t* __restrict__ C2h,
        const float* __restrict__ gamma, const float* __restrict__ beta,
        int M, int K) {
    __shared__ uint32_t As[2][128 * RS];
    __shared__ uint32_t Bs[2][128 * RS];
    __shared__ float red[2][4][128];
    const int N = 128;
    int tid  = threadIdx.x;
    int warp = tid >> 5, lane = tid & 31;
    int wm = warp >> 2;
    int wn = warp & 3;
    int t = lane & 3, g = lane >> 2;
    int m0 = blockIdx.y * 128;
    int K2 = K >> 1;

    float acc[4][4][4];
    #pragma unroll
    for (int i = 0; i < 4; i++)
        #pragma unroll
        for (int j = 0; j < 4; j++)
            #pragma unroll
            for (int r = 0; r < 4; r++) acc[i][j][r] = 0.f;

    int arow = tid >> 1;
    int aoff = (tid & 1) << 3;
    uint4 pa[2], pb[2];
    {
        const uint32_t* ap = A  + (size_t)(m0 + arow) * K2 + aoff;
        const uint32_t* bp = Wh + (size_t)arow * K2 + aoff;
        pa[0] = *(const uint4*)ap;     pa[1] = *(const uint4*)(ap + 4);
        pb[0] = *(const uint4*)bp;     pb[1] = *(const uint4*)(bp + 4);
    }

    int slabs = K >> 5;
    for (int s = 0; s < slabs; s++) {
        uint32_t* Ab = As[s & 1];
        uint32_t* Bb = Bs[s & 1];
        {
            uint4* da = (uint4*)&Ab[arow * RS + aoff];
            da[0] = pa[0]; da[1] = pa[1];
            uint4* db = (uint4*)&Bb[arow * RS + aoff];
            db[0] = pb[0]; db[1] = pb[1];
        }
        __syncthreads();
        if (s + 1 < slabs) {
            const uint32_t* ap = A  + (size_t)(m0 + arow) * K2 + (s + 1) * 16 + aoff;
            const uint32_t* bp = Wh + (size_t)arow * K2 + (s + 1) * 16 + aoff;
            pa[0] = *(const uint4*)ap;  pa[1] = *(const uint4*)(ap + 4);
            pb[0] = *(const uint4*)bp;  pb[1] = *(const uint4*)(bp + 4);
        }
        #pragma unroll
        for (int ks = 0; ks < 2; ks++) {
            uint32_t af[4][4], bf[4][2];
            #pragma unroll
            for (int i = 0; i < 4; i++) {
                const uint32_t* p = Ab + (wm * 64 + i * 16 + g) * RS + ks * 8 + t;
                af[i][0] = p[0];
                af[i][1] = p[8 * RS];
                af[i][2] = p[4];
                af[i][3] = p[8 * RS + 4];
            }
            #pragma unroll
            for (int j = 0; j < 4; j++) {
                const uint32_t* p = Bb + (wn * 32 + j * 8 + g) * RS + ks * 8 + t;
                bf[j][0] = p[0];
                bf[j][1] = p[4];
            }
            #pragma unroll
            for (int i = 0; i < 4; i++)
                #pragma unroll
                for (int j = 0; j < 4; j++)
                    mma16n8k16(acc[i][j], af[i], bf[j]);
        }
        __syncthreads();
    }

    int ncol[4];
    float bc[4][2], gc[4][2], btc[4][2], zc[4][2];
    int bidx = m0 >> 12;
    #pragma unroll
    for (int j = 0; j < 4; j++) {
        int n = wn * 32 + j * 8 + 2 * t;
        ncol[j] = n;
        bc[j][0]  = bias[n];   bc[j][1]  = bias[n + 1];
        gc[j][0]  = gamma[n];  gc[j][1]  = gamma[n + 1];
        btc[j][0] = beta[n];   btc[j][1] = beta[n + 1];
        zc[j][0]  = g_z2[bidx * C_DIM + n];
        zc[j][1]  = g_z2[bidx * C_DIM + n + 1];
    }
    #pragma unroll
    for (int i = 0; i < 4; i++) {
        #pragma unroll
        for (int half = 0; half < 2; half++) {
            int rl = wm * 64 + i * 16 + g + 8 * half;
            size_t ro = (size_t)(m0 + rl) * N;
            float s = 0.f, s2 = 0.f;
            #pragma unroll
            for (int j = 0; j < 4; j++) {
                float2 rv = *(const float2*)(res + ro + ncol[j]);
                float vx = acc[i][j][2 * half]     + bc[j][0] + rv.x;
                float vy = acc[i][j][2 * half + 1] + bc[j][1] + rv.y;
                acc[i][j][2 * half] = vx; acc[i][j][2 * half + 1] = vy;
                s += vx + vy; s2 += vx * vx + vy * vy;
            }
            s  += __shfl_xor_sync(0xffffffffu, s, 1);
            s  += __shfl_xor_sync(0xffffffffu, s, 2);
            s2 += __shfl_xor_sync(0xffffffffu, s2, 1);
            s2 += __shfl_xor_sync(0xffffffffu, s2, 2);
            if (t == 0) { red[0][wn][rl] = s; red[1][wn][rl] = s2; }
        }
    }
    __syncthreads();
    #pragma unroll
    for (int i = 0; i < 4; i++) {
        #pragma unroll
        for (int half = 0; half < 2; half++) {
            int rl = wm * 64 + i * 16 + g + 8 * half;
            float s  = red[0][0][rl] + red[0][1][rl] + red[0][2][rl] + red[0][3][rl];
            float s2 = red[1][0][rl] + red[1][1][rl] + red[1][2][rl] + red[1][3][rl];
            float mu   = s  * (1.f / 128.f);
            float var  = s2 * (1.f / 128.f) - mu * mu;
            float rstd = rsqrtf(var + 1e-5f);
            size_t ro  = (size_t)(m0 + rl) * N;
            size_t ro2 = (size_t)(m0 + rl) * 64;
            #pragma unroll
            for (int j = 0; j < 4; j++) {
                float vx = acc[i][j][2 * half];
                float vy = acc[i][j][2 * half + 1];
                *(float2*)(C + ro + ncol[j]) = make_float2(vx, vy);
                float hx = (vx - mu) * rstd * gc[j][0] + btc[j][0] + zc[j][0];
                float hy = (vy - mu) * rstd * gc[j][1] + btc[j][1] + zc[j][1];
                C2h[ro2 + (ncol[j] >> 1)] = pack_h2(hx, hy);
            }
        }
    }
}

// ---------------------------------------------------------------------------
// Barrier-free flash attention + LePE, fp16 mma, 4 CTAs/SM (single wave).
// V tile: pitch 16 words + XOR swizzle (col ^ ((row>>1)&1)<<3); the ones
// column (row sums) is synthesized as a register B-fragment.
// smem: 16*520 (Q,K) + 256*16 (V) + 160 (LePE) = 12576 words = 50.3KB.
// ---------------------------------------------------------------------------
#define QP 520
#define OFF_QH 0
#define OFF_KH (8*QP)
#define OFF_VH (16*QP)
#define OFF_W  (OFF_VH + 256*16)
#define OFF_B  (OFF_W + 144)
#define ATTN_SMEM_WORDS (OFF_B + 16)
#define H2_ONE 0x3C003C00u

__device__ __forceinline__ int tok_to_l(int n, int br, int wn) {
    if (br == 0) { int h = n >> 3, w = n & 7; return h * 64 + wn * 8 + w; }
    return wn * 512 + n;
}

__global__ void __launch_bounds__(256, 4) attn_kernel(
        const float* __restrict__ lepe_w0, const float* __restrict__ lepe_b0,
        const float* __restrict__ lepe_w1, const float* __restrict__ lepe_b1) {
    extern __shared__ uint32_t smw[];
    uint32_t* Qh  = smw + OFF_QH;
    uint32_t* Kh  = smw + OFF_KH;
    uint32_t* Vh  = smw + OFF_VH;
    float*    wsm = (float*)(smw + OFF_W);
    float*    bsm = (float*)(smw + OFF_B);

    int wglob = blockIdx.x;
    int hd    = blockIdx.y;
    int br    = blockIdx.z;
    int b  = wglob >> 3;
    int wn = wglob & 7;
    int cb = br * 64 + hd * 16;
    int cw = cb >> 1;
    int tid  = threadIdx.x;
    int warp = tid >> 5, lane = tid & 31;
    int g = lane >> 2, t = lane & 3;

    {
        int tp = tid;
        int t0 = tp * 2, t1 = t0 + 1;
        int l0 = tok_to_l(t0, br, wn), l1 = tok_to_l(t1, br, wn);
        const uint32_t* p0 = g_qkvh + (size_t)(b * L_DIM + l0) * 192 + cw;
        const uint32_t* p1 = g_qkvh + (size_t)(b * L_DIM + l1) * 192 + cw;
        uint4 qa0 = *(const uint4*)(p0);       uint4 qa1 = *(const uint4*)(p0 + 4);
        uint4 qb0 = *(const uint4*)(p1);       uint4 qb1 = *(const uint4*)(p1 + 4);
        Qh[0*QP+t0]=qa0.x; Qh[1*QP+t0]=qa0.y; Qh[2*QP+t0]=qa0.z; Qh[3*QP+t0]=qa0.w;
        Qh[4*QP+t0]=qa1.x; Qh[5*QP+t0]=qa1.y; Qh[6*QP+t0]=qa1.z; Qh[7*QP+t0]=qa1.w;
        Qh[0*QP+t1]=qb0.x; Qh[1*QP+t1]=qb0.y; Qh[2*QP+t1]=qb0.z; Qh[3*QP+t1]=qb0.w;
        Qh[4*QP+t1]=qb1.x; Qh[5*QP+t1]=qb1.y; Qh[6*QP+t1]=qb1.z; Qh[7*QP+t1]=qb1.w;
        uint4 ka0 = *(const uint4*)(p0 + 64);  uint4 ka1 = *(const uint4*)(p0 + 68);
        uint4 kb0 = *(const uint4*)(p1 + 64);  uint4 kb1 = *(const uint4*)(p1 + 68);
        Kh[0*QP+t0]=ka0.x; Kh[1*QP+t0]=ka0.y; Kh[2*QP+t0]=ka0.z; Kh[3*QP+t0]=ka0.w;
        Kh[4*QP+t0]=ka1.x; Kh[5*QP+t0]=ka1.y; Kh[6*QP+t0]=ka1.z; Kh[7*QP+t0]=ka1.w;
        Kh[0*QP+t1]=kb0.x; Kh[1*QP+t1]=kb0.y; Kh[2*QP+t1]=kb0.z; Kh[3*QP+t1]=kb0.w;
        Kh[4*QP+t1]=kb1.x; Kh[5*QP+t1]=kb1.y; Kh[6*QP+t1]=kb1.z; Kh[7*QP+t1]=kb1.w;
        uint4 va0 = *(const uint4*)(p0 + 128); uint4 va1 = *(const uint4*)(p0 + 132);
        uint4 vb0 = *(const uint4*)(p1 + 128); uint4 vb1 = *(const uint4*)(p1 + 132);
        uint32_t wa[8] = {va0.x, va0.y, va0.z, va0.w, va1.x, va1.y, va1.z, va1.w};
        uint32_t wb[8] = {vb0.x, vb0.y, vb0.z, vb0.w, vb1.x, vb1.y, vb1.z, vb1.w};
        uint32_t* vr = Vh + tp * 16;
        int sv = ((tp >> 1) & 1) << 3;        // V swizzle bit for this row
        #pragma unroll
        for (int i = 0; i < 8; i++) {
            vr[(2*i)     ^ sv] = __byte_perm(wa[i], wb[i], 0x5410);
            vr[(2*i + 1) ^ sv] = __byte_perm(wa[i], wb[i], 0x7632);
        }
    }
    const float* lw = br ? lepe_w1 : lepe_w0;
    const float* lb = br ? lepe_b1 : lepe_b0;
    if (tid < 144) wsm[tid] = lw[hd * 16 * 9 + tid] * INV_SC;
    if (tid < 16)  bsm[tid] = lb[hd * 16 + tid];
    __syncthreads();

    const int HS = br ? 8 : 64;
    const int WS = br ? 64 : 8;
    // V read swizzle: rows kh+t and kh+t+4 (kh % 8 == 0) share bit (t>>1)&1.
    const int svr = (t >> 1) & 1;
    const uint32_t ones_b = (g == 0) ? H2_ONE : 0u;

    #pragma unroll 1
    for (int pass = 0; pass < 4; pass++) {
        int qb = pass * 128 + warp * 16;

        uint32_t af[4];
        af[0] = Qh[t * QP + qb + g];
        af[1] = Qh[t * QP + qb + g + 8];
        af[2] = Qh[(t + 4) * QP + qb + g];
        af[3] = Qh[(t + 4) * QP + qb + g + 8];

        float m0 = -1e30f, m1 = -1e30f;
        float oacc[3][4];
        #pragma unroll
        for (int j = 0; j < 3; j++) {
            oacc[j][0] = 0.f; oacc[j][1] = 0.f;
            oacc[j][2] = 0.f; oacc[j][3] = 0.f;
        }

        #pragma unroll 1
        for (int c = 0; c < 8; c++) {
            int kb = c * 64;
            float sacc[8][4];
            #pragma unroll
            for (int j = 0; j < 8; j++) {
                sacc[j][0] = 0.f; sacc[j][1] = 0.f;
                sacc[j][2] = 0.f; sacc[j][3] = 0.f;
                uint32_t bf[2];
                bf[0] = Kh[t * QP + kb + j * 8 + g];
                bf[1] = Kh[(t + 4) * QP + kb + j * 8 + g];
                mma16n8k16(sacc[j], af, bf);
            }
            float mx0 = sacc[0][0], mx1 = sacc[0][2];
            #pragma unroll
            for (int j = 0; j < 8; j++) {
                mx0 = fmaxf(mx0, fmaxf(sacc[j][0], sacc[j][1]));
                mx1 = fmaxf(mx1, fmaxf(sacc[j][2], sacc[j][3]));
            }
            mx0 = fmaxf(mx0, __shfl_xor_sync(0xffffffffu, mx0, 1));
            mx0 = fmaxf(mx0, __shfl_xor_sync(0xffffffffu, mx0, 2));
            mx1 = fmaxf(mx1, __shfl_xor_sync(0xffffffffu, mx1, 1));
            mx1 = fmaxf(mx1, __shfl_xor_sync(0xffffffffu, mx1, 2));
            float mn0 = fmaxf(m0, mx0), mn1 = fmaxf(m1, mx1);
            float a0 = fast_ex2(m0 - mn0), a1 = fast_ex2(m1 - mn1);
            m0 = mn0; m1 = mn1;
            #pragma unroll
            for (int j = 0; j < 3; j++) {
                oacc[j][0] *= a0; oacc[j][1] *= a0;
                oacc[j][2] *= a1; oacc[j][3] *= a1;
            }
            #pragma unroll
            for (int ks = 0; ks < 4; ks++) {
                uint32_t pf[4];
                pf[0] = ex2_h2(pack_h2(sacc[2*ks][0]   - m0, sacc[2*ks][1]   - m0));
                pf[1] = ex2_h2(pack_h2(sacc[2*ks][2]   - m1, sacc[2*ks][3]   - m1));
                pf[2] = ex2_h2(pack_h2(sacc[2*ks+1][0] - m0, sacc[2*ks+1][1] - m0));
                pf[3] = ex2_h2(pack_h2(sacc[2*ks+1][2] - m1, sacc[2*ks+1][3] - m1));
                int kh = c * 32 + ks * 8;
                #pragma unroll
                for (int j = 0; j < 2; j++) {
                    int jj = j ^ svr;                       // swizzled tile
                    uint32_t bf[2];
                    bf[0] = Vh[(kh + t) * 16 + jj * 8 + g];
                    bf[1] = Vh[(kh + t + 4) * 16 + jj * 8 + g];
                    mma16n8k16(oacc[j], pf, bf);
                }
                {   // ones tile (row sums): register B-fragment
                    uint32_t bf[2] = { ones_b, ones_b };
                    mma16n8k16(oacc[2], pf, bf);
                }
            }
        }

        float l0 = __shfl_sync(0xffffffffu, oacc[2][0], lane & 28);
        float l1 = __shfl_sync(0xffffffffu, oacc[2][2], lane & 28);
        float inv0 = 1.f / l0, inv1 = 1.f / l1;

        #pragma unroll
        for (int half = 0; half < 2; half++) {
            int n = qb + g + 8 * half;
            int hq = n / WS, wq = n % WS;
            float inv = half ? inv1 : inv0;
            int l = tok_to_l(n, br, wn);
            uint32_t* orow = g_atth + (size_t)(b * L_DIM + l) * 64 + cw;
            #pragma unroll
            for (int j = 0; j < 2; j++) {
                int d0 = j * 8 + 2 * t;
                float lp0 = bsm[d0], lp1 = bsm[d0 + 1];
                #pragma unroll
                for (int ky = 0; ky < 3; ky++) {
                    int hh = hq + ky - 1;
                    if (hh < 0 || hh >= HS) continue;
                    #pragma unroll
                    for (int kx = 0; kx < 3; kx++) {
                        int ww = wq + kx - 1;
                        if (ww < 0 || ww >= WS) continue;
                        uint32_t u = Qh[(j * 4 + t) * QP + hh * WS + ww];
                        float2 qf = __half22float2(*(__half2*)&u);
                        lp0 = fmaf(wsm[d0 * 9 + ky * 3 + kx], qf.x, lp0);
                        lp1 = fmaf(wsm[(d0 + 1) * 9 + ky * 3 + kx], qf.y, lp1);
                    }
                }
                float v0 = oacc[j][2 * half]     * inv + lp0;
                float v1 = oacc[j][2 * half + 1] * inv + lp1;
                orow[d0 >> 1] = pack_h2(v0, v1);
            }
        }
    }
}

// ---------------------------------------------------------------------------
extern "C" void kernel_launch(void* const* d_in, const int* in_sizes, int n_in,
                              void* d_out, int out_size) {
    const float* x       = (const float*)d_in[0];
    const float* z       = (const float*)d_in[1];
    const float* ln1_g   = (const float*)d_in[2];
    const float* ln1_b   = (const float*)d_in[3];
    const float* ln2_g   = (const float*)d_in[4];
    const float* ln2_b   = (const float*)d_in[5];
    const float* Wz1     = (const float*)d_in[6];
    const float* Wz2     = (const float*)d_in[7];
    const float* Wqkv    = (const float*)d_in[8];
    const float* Wproj   = (const float*)d_in[9];
    const float* bproj   = (const float*)d_in[10];
    const float* lepe_w0 = (const float*)d_in[11];
    const float* lepe_b0 = (const float*)d_in[12];
    const float* lepe_w1 = (const float*)d_in[13];
    const float* lepe_b1 = (const float*)d_in[14];
    const float* W1      = (const float*)d_in[15];
    const float* b1      = (const float*)d_in[16];
    const float* W2      = (const float*)d_in[17];
    const float* b2      = (const float*)d_in[18];
    float* out = (float*)d_out;

    float*    p_xf;    cudaGetSymbolAddress((void**)&p_xf,    g_xf);
    float*    p_xf2;   cudaGetSymbolAddress((void**)&p_xf2,   g_xf2);
    uint32_t* p_h1h;   cudaGetSymbolAddress((void**)&p_h1h,   g_h1h);
    uint32_t* p_qkvh;  cudaGetSymbolAddress((void**)&p_qkvh,  g_qkvh);
    uint32_t* p_atth;  cudaGetSymbolAddress((void**)&p_atth,  g_atth);
    uint32_t* p_h2h;   cudaGetSymbolAddress((void**)&p_h2h,   g_h2h);
    uint32_t* p_midh;  cudaGetSymbolAddress((void**)&p_midh,  g_midh);
    uint32_t* p_wqkvh; cudaGetSymbolAddress((void**)&p_wqkvh, g_wqkvh);
    uint32_t* p_wprojh;cudaGetSymbolAddress((void**)&p_wprojh,g_wprojh);
    uint32_t* p_w1h;   cudaGetSymbolAddress((void**)&p_w1h,   g_w1h);
    uint32_t* p_w2h;   cudaGetSymbolAddress((void**)&p_w2h,   g_w2h);

    const int attn_smem = ATTN_SMEM_WORDS * (int)sizeof(uint32_t);
    cudaFuncSetAttribute(attn_kernel, cudaFuncAttributeMaxDynamicSharedMemorySize, attn_smem);

    // 1) z projections + weight fp16 conversion
    prep_kernel<<<56, 256>>>(z, Wz1, Wz2, Wqkv, Wproj, W1, W2);
    // 2) transpose + LN1 (+z1): xf fp32, h1 fp16
    ln1_kernel<<<dim3(128, 8), 256>>>(x, ln1_g, ln1_b);
    // 3) qkv = h1 @ Wqkv^T  -> fp16, Q pre-scaled
    gemm_h<1><<<dim3(QKV_N / 128, M_ROWS / 128), 256>>>(
        p_h1h, p_wqkvh, nullptr, nullptr, p_qkvh, M_ROWS, QKV_N, C_DIM, 0, 1);
    // 4) windowed attention + LePE -> att fp16
    attn_kernel<<<dim3(64, 4, 2), 256, attn_smem>>>(lepe_w0, lepe_b0, lepe_w1, lepe_b1);
    // 5) xf2 = xf + att @ Wproj^T + bproj (fp32);  h2 = LN2(xf2)+z2 (fp16)
    gemm_ln_kernel<<<dim3(1, M_ROWS / 128), 256>>>(
        p_atth, p_wprojh, bproj, p_xf, p_xf2, p_h2h, ln2_g, ln2_b, M_ROWS, C_DIM);
    // 6) mid = gelu(h2 @ W1^T + b1) -> fp16
    gemm_h<1><<<dim3(HID / 128, M_ROWS / 128), 256>>>(
        p_h2h, p_w1h, b1, nullptr, p_midh, M_ROWS, HID, C_DIM, 1, 0);
    // 7) out = T(xf2 + mid @ W2^T + b2)  -> (B,C,H,W), fused transpose
    gemm_trans_kernel<<<dim3(1, M_ROWS / 128), 256>>>(
        p_midh, p_w2h, b2, p_xf2, out, M_ROWS, HID);
}

// round 16
// speedup vs baseline: 1.5815x; 1.5815x over previous
#include <cuda_runtime.h>
#include <cuda_bf16.h>
#include <cuda_fp16.h>
#include <cstdint>
#include <math.h>

// ---------------------------------------------------------------------------
// Problem constants
// ---------------------------------------------------------------------------
#define M_ROWS   32768
#define C_DIM    128
#define L_DIM    4096
#define B_DIM    8
#define HID      512
#define QKV_N    384
#define ZC       512

// ---------------------------------------------------------------------------
// Scratch buffers.  fp16 tensors stored as packed half2 words (uint32).
// ---------------------------------------------------------------------------
__device__ __align__(16) float    g_xf  [M_ROWS * C_DIM];
__device__ __align__(16) float    g_xf2 [M_ROWS * C_DIM];
__device__ __align__(16) uint32_t g_h1h [M_ROWS * (C_DIM/2)];
__device__ __align__(16) uint32_t g_qkvh[M_ROWS * (QKV_N/2)];
__device__ __align__(16) uint32_t g_atth[M_ROWS * (C_DIM/2)];
__device__ __align__(16) uint32_t g_h2h [M_ROWS * (C_DIM/2)];
__device__ __align__(16) uint32_t g_midh[M_ROWS * (HID/2)];
__device__ __align__(16) float    g_z1  [B_DIM * C_DIM];
__device__ __align__(16) float    g_z2  [B_DIM * C_DIM];
// fp16 weights (packed half2 along K)
__device__ __align__(16) uint32_t g_wqkvh[QKV_N * (C_DIM/2)];
__device__ __align__(16) uint32_t g_wprojh[C_DIM * (C_DIM/2)];
__device__ __align__(16) uint32_t g_w1h  [HID * (C_DIM/2)];
__device__ __align__(16) uint32_t g_w2h  [C_DIM * (HID/2)];

#define SOFTMAX_SC 0.36067376022224085f   // 0.25 * log2(e)
#define INV_SC     2.7725887222397811f    // 1 / SOFTMAX_SC = 4 ln 2

// ---------------------------------------------------------------------------
// helpers
// ---------------------------------------------------------------------------
__device__ __forceinline__ uint32_t pack_h2(float lo, float hi) {
    uint32_t u;
    asm("cvt.rn.f16x2.f32 %0, %1, %2;" : "=r"(u) : "f"(hi), "f"(lo));
    return u;
}
__device__ __forceinline__ uint32_t ex2_h2(uint32_t h2) {
    uint32_t r;
    asm("ex2.approx.f16x2 %0, %1;" : "=r"(r) : "r"(h2));
    return r;
}
__device__ __forceinline__ float fast_ex2(float x) {
    float y;
    asm("ex2.approx.ftz.f32 %0, %1;" : "=f"(y) : "f"(x));
    return y;
}
__device__ __forceinline__ float gelu_f(float v) {
    return 0.5f * v * (1.f + erff(v * 0.70710678118654752f));
}
__device__ __forceinline__ void mma16n8k16(float* d, const uint32_t* a,
                                           const uint32_t* b) {
    asm("mma.sync.aligned.m16n8k16.row.col.f32.f16.f16.f32 "
        "{%0,%1,%2,%3}, {%4,%5,%6,%7}, {%8,%9}, {%0,%1,%2,%3};"
        : "+f"(d[0]), "+f"(d[1]), "+f"(d[2]), "+f"(d[3])
        : "r"(a[0]), "r"(a[1]), "r"(a[2]), "r"(a[3]), "r"(b[0]), "r"(b[1]));
}

// ---------------------------------------------------------------------------
// prep: z projections (blocks 0-7) + weight fp16 conversion (blocks 8-55)
// ---------------------------------------------------------------------------
__global__ void prep_kernel(const float* __restrict__ z,
                            const float* __restrict__ Wz1,
                            const float* __restrict__ Wz2,
                            const float* __restrict__ Wqkv,
                            const float* __restrict__ Wproj,
                            const float* __restrict__ W1,
                            const float* __restrict__ W2) {
    if (blockIdx.x < 8) {
        int o = blockIdx.x * 256 + threadIdx.x;
        int which = o >> 10;
        int b = (o >> 7) & 7;
        int c = o & 127;
        const float* W = (which ? Wz2 : Wz1) + c * ZC;
        const float* zb = z + b * ZC;
        float s = 0.f;
        #pragma unroll 8
        for (int k = 0; k < ZC; k++) s += zb[k] * W[k];
        (which ? g_z2 : g_z1)[b * C_DIM + c] = s;
        return;
    }
    int idx = (blockIdx.x - 8) * 2048 + threadIdx.x * 8;
    const float* src; uint32_t* dst; int base;
    if (idx < 24576)      { src = Wqkv;  dst = g_wqkvh;  base = idx; }
    else if (idx < 32768) { src = Wproj; dst = g_wprojh; base = idx - 24576; }
    else if (idx < 65536) { src = W1;    dst = g_w1h;    base = idx - 32768; }
    else                  { src = W2;    dst = g_w2h;    base = idx - 65536; }
    const float* s = src + (size_t)base * 2;
    uint32_t w[8];
    #pragma unroll
    for (int i = 0; i < 4; i++) {
        float4 v = ((const float4*)s)[i];
        w[2*i]   = pack_h2(v.x, v.y);
        w[2*i+1] = pack_h2(v.z, v.w);
    }
    uint4 o0 = {w[0], w[1], w[2], w[3]};
    uint4 o1 = {w[4], w[5], w[6], w[7]};
    *(uint4*)(dst + base)     = o0;
    *(uint4*)(dst + base + 4) = o1;
}

// ---------------------------------------------------------------------------
// Transpose x -> xf (fp32) and h1 = LN(xf)+z1 packed fp16.
// ---------------------------------------------------------------------------
__global__ void __launch_bounds__(256) ln1_kernel(const float* __restrict__ x,
                                                  const float* __restrict__ gamma,
                                                  const float* __restrict__ beta) {
    __shared__ float sm[128][33];
    int b  = blockIdx.y;
    int l0 = blockIdx.x * 32;
    int tid = threadIdx.x;
    const float* xb = x + (size_t)b * C_DIM * L_DIM;
    #pragma unroll
    for (int r = 0; r < 16; r++) {
        int c = r * 8 + (tid >> 5);
        int j = tid & 31;
        sm[c][j] = xb[(size_t)c * L_DIM + l0 + j];
    }
    __syncthreads();
    int warp = tid >> 5, lane = tid & 31;
    #pragma unroll
    for (int rr = 0; rr < 4; rr++) {
        int j = warp + rr * 8;
        float v[4];
        v[0] = sm[2 * lane][j];
        v[1] = sm[2 * lane + 1][j];
        v[2] = sm[64 + 2 * lane][j];
        v[3] = sm[65 + 2 * lane][j];
        float s = v[0] + v[1] + v[2] + v[3];
        float s2 = v[0]*v[0] + v[1]*v[1] + v[2]*v[2] + v[3]*v[3];
        #pragma unroll
        for (int o = 16; o; o >>= 1) {
            s  += __shfl_xor_sync(0xffffffffu, s,  o);
            s2 += __shfl_xor_sync(0xffffffffu, s2, o);
        }
        float mu   = s  * (1.f / 128.f);
        float var  = s2 * (1.f / 128.f) - mu * mu;
        float rstd = rsqrtf(var + 1e-5f);
        int l = l0 + j;
        size_t row = (size_t)b * L_DIM + l;
        float* xfr = g_xf + row * C_DIM;
        *(float2*)(xfr + 2 * lane)      = make_float2(v[0], v[1]);
        *(float2*)(xfr + 64 + 2 * lane) = make_float2(v[2], v[3]);
        const float* z1b = g_z1 + b * C_DIM;
        float h[4];
        #pragma unroll
        for (int u = 0; u < 4; u++) {
            int c = (u < 2) ? (2 * lane + u) : (62 + 2 * lane + u);
            h[u] = (v[u] - mu) * rstd * gamma[c] + beta[c] + z1b[c];
        }
        uint32_t* hr = g_h1h + row * 64;
        hr[lane]      = pack_h2(h[0], h[1]);
        hr[32 + lane] = pack_h2(h[2], h[3]);
    }
}

// ---------------------------------------------------------------------------
// Lean tensor-core GEMM, BK=32, both operands fp16 words, [row][RS] smem.
// CH=0: C fp32 with optional res;  CH=1: C fp16 words, optional qscale.
// ---------------------------------------------------------------------------
#define RS 20

template<int CH>
__global__ void __launch_bounds__(256) gemm_h(
        const uint32_t* __restrict__ A, const uint32_t* __restrict__ Wh,
        const float* __restrict__ bias, const float* __restrict__ res,
        void* __restrict__ Cv, int M, int N, int K, int act, int qsc) {
    __shared__ uint32_t As[2][128 * RS];
    __shared__ uint32_t Bs[2][128 * RS];
    int tid  = threadIdx.x;
    int warp = tid >> 5, lane = tid & 31;
    int wm = warp >> 2;
    int wn = warp & 3;
    int t = lane & 3, g = lane >> 2;
    int m0 = blockIdx.y * 128, n0 = blockIdx.x * 128;
    int K2 = K >> 1;

    float acc[4][4][4];
    #pragma unroll
    for (int i = 0; i < 4; i++)
        #pragma unroll
        for (int j = 0; j < 4; j++)
            #pragma unroll
            for (int r = 0; r < 4; r++) acc[i][j][r] = 0.f;

    int arow = tid >> 1;
    int aoff = (tid & 1) << 3;
    uint4 pa[2], pb[2];
    {
        const uint32_t* ap = A  + (size_t)(m0 + arow) * K2 + aoff;
        const uint32_t* bp = Wh + (size_t)(n0 + arow) * K2 + aoff;
        pa[0] = *(const uint4*)ap;     pa[1] = *(const uint4*)(ap + 4);
        pb[0] = *(const uint4*)bp;     pb[1] = *(const uint4*)(bp + 4);
    }

    int slabs = K >> 5;
    for (int s = 0; s < slabs; s++) {
        uint32_t* Ab = As[s & 1];
        uint32_t* Bb = Bs[s & 1];
        {
            uint4* da = (uint4*)&Ab[arow * RS + aoff];
            da[0] = pa[0]; da[1] = pa[1];
            uint4* db = (uint4*)&Bb[arow * RS + aoff];
            db[0] = pb[0]; db[1] = pb[1];
        }
        __syncthreads();
        if (s + 1 < slabs) {
            const uint32_t* ap = A  + (size_t)(m0 + arow) * K2 + (s + 1) * 16 + aoff;
            const uint32_t* bp = Wh + (size_t)(n0 + arow) * K2 + (s + 1) * 16 + aoff;
            pa[0] = *(const uint4*)ap;  pa[1] = *(const uint4*)(ap + 4);
            pb[0] = *(const uint4*)bp;  pb[1] = *(const uint4*)(bp + 4);
        }
        #pragma unroll
        for (int ks = 0; ks < 2; ks++) {
            uint32_t af[4][4], bf[4][2];
            #pragma unroll
            for (int i = 0; i < 4; i++) {
                const uint32_t* p = Ab + (wm * 64 + i * 16 + g) * RS + ks * 8 + t;
                af[i][0] = p[0];
                af[i][1] = p[8 * RS];
                af[i][2] = p[4];
                af[i][3] = p[8 * RS + 4];
            }
            #pragma unroll
            for (int j = 0; j < 4; j++) {
                const uint32_t* p = Bb + (wn * 32 + j * 8 + g) * RS + ks * 8 + t;
                bf[j][0] = p[0];
                bf[j][1] = p[4];
            }
            #pragma unroll
            for (int i = 0; i < 4; i++)
                #pragma unroll
                for (int j = 0; j < 4; j++)
                    mma16n8k16(acc[i][j], af[i], bf[j]);
        }
        __syncthreads();
    }

    if (CH == 0) {
        float* C = (float*)Cv;
        #pragma unroll
        for (int i = 0; i < 4; i++) {
            int mr = m0 + wm * 64 + i * 16 + g;
            #pragma unroll
            for (int half = 0; half < 2; half++) {
                int m = mr + 8 * half;
                size_t ro = (size_t)m * N;
                #pragma unroll
                for (int j = 0; j < 4; j++) {
                    int n = n0 + wn * 32 + j * 8 + 2 * t;
                    float vx = acc[i][j][2 * half];
                    float vy = acc[i][j][2 * half + 1];
                    if (bias) { vx += bias[n]; vy += bias[n + 1]; }
                    if (res) {
                        float2 rv = *(const float2*)(res + ro + n);
                        vx += rv.x; vy += rv.y;
                    }
                    if (act) { vx = gelu_f(vx); vy = gelu_f(vy); }
                    *(float2*)(C + ro + n) = make_float2(vx, vy);
                }
            }
        }
    } else {
        uint32_t* Ch = (uint32_t*)Cv;
        int N2 = N >> 1;
        #pragma unroll
        for (int i = 0; i < 4; i++) {
            int mr = m0 + wm * 64 + i * 16 + g;
            #pragma unroll
            for (int half = 0; half < 2; half++) {
                int m = mr + 8 * half;
                size_t ro = (size_t)m * N2;
                #pragma unroll
                for (int j = 0; j < 4; j++) {
                    int n = n0 + wn * 32 + j * 8 + 2 * t;
                    float vx = acc[i][j][2 * half];
                    float vy = acc[i][j][2 * half + 1];
                    if (bias) { vx += bias[n]; vy += bias[n + 1]; }
                    if (act) { vx = gelu_f(vx); vy = gelu_f(vy); }
                    if (qsc && n < 128) { vx *= SOFTMAX_SC; vy *= SOFTMAX_SC; }
                    Ch[ro + (n >> 1)] = pack_h2(vx, vy);
                }
            }
        }
    }
}

// ---------------------------------------------------------------------------
// mlp2 GEMM with fused output transpose (reused GEMM smem, no extra shared).
// ---------------------------------------------------------------------------
__global__ void __launch_bounds__(256) gemm_trans_kernel(
        const uint32_t* __restrict__ A, const uint32_t* __restrict__ Wh,
        const float* __restrict__ bias, const float* __restrict__ res,
        float* __restrict__ Cout, int M, int K) {
    __shared__ __align__(16) union {
        uint32_t buf[4][128 * RS];
        float    ts[64 * 132];
    } smu;
    const int N = 128;
    int tid  = threadIdx.x;
    int warp = tid >> 5, lane = tid & 31;
    int wm = warp >> 2;
    int wn = warp & 3;
    int t = lane & 3, g = lane >> 2;
    int m0 = blockIdx.y * 128;
    int K2 = K >> 1;

    float acc[4][4][4];
    #pragma unroll
    for (int i = 0; i < 4; i++)
        #pragma unroll
        for (int j = 0; j < 4; j++)
            #pragma unroll
            for (int r = 0; r < 4; r++) acc[i][j][r] = 0.f;

    int arow = tid >> 1;
    int aoff = (tid & 1) << 3;
    uint4 pa[2], pb[2];
    {
        const uint32_t* ap = A  + (size_t)(m0 + arow) * K2 + aoff;
        const uint32_t* bp = Wh + (size_t)arow * K2 + aoff;
        pa[0] = *(const uint4*)ap;     pa[1] = *(const uint4*)(ap + 4);
        pb[0] = *(const uint4*)bp;     pb[1] = *(const uint4*)(bp + 4);
    }

    int slabs = K >> 5;
    for (int s = 0; s < slabs; s++) {
        uint32_t* Ab = smu.buf[s & 1];
        uint32_t* Bb = smu.buf[2 + (s & 1)];
        {
            uint4* da = (uint4*)&Ab[arow * RS + aoff];
            da[0] = pa[0]; da[1] = pa[1];
            uint4* db = (uint4*)&Bb[arow * RS + aoff];
            db[0] = pb[0]; db[1] = pb[1];
        }
        __syncthreads();
        if (s + 1 < slabs) {
            const uint32_t* ap = A  + (size_t)(m0 + arow) * K2 + (s + 1) * 16 + aoff;
            const uint32_t* bp = Wh + (size_t)arow * K2 + (s + 1) * 16 + aoff;
            pa[0] = *(const uint4*)ap;  pa[1] = *(const uint4*)(ap + 4);
            pb[0] = *(const uint4*)bp;  pb[1] = *(const uint4*)(bp + 4);
        }
        #pragma unroll
        for (int ks = 0; ks < 2; ks++) {
            uint32_t af[4][4], bf[4][2];
            #pragma unroll
            for (int i = 0; i < 4; i++) {
                const uint32_t* p = Ab + (wm * 64 + i * 16 + g) * RS + ks * 8 + t;
                af[i][0] = p[0];
                af[i][1] = p[8 * RS];
                af[i][2] = p[4];
                af[i][3] = p[8 * RS + 4];
            }
            #pragma unroll
            for (int j = 0; j < 4; j++) {
                const uint32_t* p = Bb + (wn * 32 + j * 8 + g) * RS + ks * 8 + t;
                bf[j][0] = p[0];
                bf[j][1] = p[4];
            }
            #pragma unroll
            for (int i = 0; i < 4; i++)
                #pragma unroll
                for (int j = 0; j < 4; j++)
                    mma16n8k16(acc[i][j], af[i], bf[j]);
        }
        __syncthreads();
    }

    int b  = m0 >> 12;
    int l0 = m0 & (L_DIM - 1);
    #pragma unroll
    for (int cc = 0; cc < 2; cc++) {
        if ((wn >> 1) == cc) {
            #pragma unroll
            for (int i = 0; i < 4; i++) {
                #pragma unroll
                for (int half = 0; half < 2; half++) {
                    int ml = wm * 64 + i * 16 + g + 8 * half;
                    size_t ro = (size_t)(m0 + ml) * N;
                    #pragma unroll
                    for (int j = 0; j < 4; j++) {
                        int n = wn * 32 + j * 8 + 2 * t;
                        float vx = acc[i][j][2 * half]     + bias[n];
                        float vy = acc[i][j][2 * half + 1] + bias[n + 1];
                        float2 rv = *(const float2*)(res + ro + n);
                        vx += rv.x; vy += rv.y;
                        int nn = n - cc * 64;
                        smu.ts[nn * 132 + ml]       = vx;
                        smu.ts[(nn + 1) * 132 + ml] = vy;
                    }
                }
            }
        }
        __syncthreads();
        #pragma unroll
        for (int it = 0; it < 8; it++) {
            int cl = warp * 8 + it;
            int c  = cc * 64 + cl;
            float4 v = *(const float4*)&smu.ts[cl * 132 + lane * 4];
            *(float4*)(Cout + ((size_t)b * C_DIM + c) * L_DIM + l0 + lane * 4) = v;
        }
        if (cc == 0) __syncthreads();
    }
}

// ---------------------------------------------------------------------------
// proj GEMM with fused LN2 (BK=32, fp16 weights).  N == 128, gridDim.x == 1.
// ---------------------------------------------------------------------------
__global__ void __launch_bounds__(256) gemm_ln_kernel(
        const uint32_t* __restrict__ A, const uint32_t* __restrict__ Wh,
        const float* __restrict__ bias, const float* __restrict__ res,
        float* __restrict__ C, uint32_t* __restrict__ C2h,
        const float* __restrict__ gamma, const float* __restrict__ beta,
        int M, int K) {
    __shared__ uint32_t As[2][128 * RS];
    __shared__ uint32_t Bs[2][128 * RS];
    __shared__ float red[2][4][128];
    const int N = 128;
    int tid  = threadIdx.x;
    int warp = tid >> 5, lane = tid & 31;
    int wm = warp >> 2;
    int wn = warp & 3;
    int t = lane & 3, g = lane >> 2;
    int m0 = blockIdx.y * 128;
    int K2 = K >> 1;

    float acc[4][4][4];
    #pragma unroll
    for (int i = 0; i < 4; i++)
        #pragma unroll
        for (int j = 0; j < 4; j++)
            #pragma unroll
            for (int r = 0; r < 4; r++) acc[i][j][r] = 0.f;

    int arow = tid >> 1;
    int aoff = (tid & 1) << 3;
    uint4 pa[2], pb[2];
    {
        const uint32_t* ap = A  + (size_t)(m0 + arow) * K2 + aoff;
        const uint32_t* bp = Wh + (size_t)arow * K2 + aoff;
        pa[0] = *(const uint4*)ap;     pa[1] = *(const uint4*)(ap + 4);
        pb[0] = *(const uint4*)bp;     pb[1] = *(const uint4*)(bp + 4);
    }

    int slabs = K >> 5;
    for (int s = 0; s < slabs; s++) {
        uint32_t* Ab = As[s & 1];
        uint32_t* Bb = Bs[s & 1];
        {
            uint4* da = (uint4*)&Ab[arow * RS + aoff];
            da[0] = pa[0]; da[1] = pa[1];
            uint4* db = (uint4*)&Bb[arow * RS + aoff];
            db[0] = pb[0]; db[1] = pb[1];
        }
        __syncthreads();
        if (s + 1 < slabs) {
            const uint32_t* ap = A  + (size_t)(m0 + arow) * K2 + (s + 1) * 16 + aoff;
            const uint32_t* bp = Wh + (size_t)arow * K2 + (s + 1) * 16 + aoff;
            pa[0] = *(const uint4*)ap;  pa[1] = *(const uint4*)(ap + 4);
            pb[0] = *(const uint4*)bp;  pb[1] = *(const uint4*)(bp + 4);
        }
        #pragma unroll
        for (int ks = 0; ks < 2; ks++) {
            uint32_t af[4][4], bf[4][2];
            #pragma unroll
            for (int i = 0; i < 4; i++) {
                const uint32_t* p = Ab + (wm * 64 + i * 16 + g) * RS + ks * 8 + t;
                af[i][0] = p[0];
                af[i][1] = p[8 * RS];
                af[i][2] = p[4];
                af[i][3] = p[8 * RS + 4];
            }
            #pragma unroll
            for (int j = 0; j < 4; j++) {
                const uint32_t* p = Bb + (wn * 32 + j * 8 + g) * RS + ks * 8 + t;
                bf[j][0] = p[0];
                bf[j][1] = p[4];
            }
            #pragma unroll
            for (int i = 0; i < 4; i++)
                #pragma unroll
                for (int j = 0; j < 4; j++)
                    mma16n8k16(acc[i][j], af[i], bf[j]);
        }
        __syncthreads();
    }

    int ncol[4];
    float bc[4][2], gc[4][2], btc[4][2], zc[4][2];
    int bidx = m0 >> 12;
    #pragma unroll
    for (int j = 0; j < 4; j++) {
        int n = wn * 32 + j * 8 + 2 * t;
        ncol[j] = n;
        bc[j][0]  = bias[n];   bc[j][1]  = bias[n + 1];
        gc[j][0]  = gamma[n];  gc[j][1]  = gamma[n + 1];
        btc[j][0] = beta[n];   btc[j][1] = beta[n + 1];
        zc[j][0]  = g_z2[bidx * C_DIM + n];
        zc[j][1]  = g_z2[bidx * C_DIM + n + 1];
    }
    #pragma unroll
    for (int i = 0; i < 4; i++) {
        #pragma unroll
        for (int half = 0; half < 2; half++) {
            int rl = wm * 64 + i * 16 + g + 8 * half;
            size_t ro = (size_t)(m0 + rl) * N;
            float s = 0.f, s2 = 0.f;
            #pragma unroll
            for (int j = 0; j < 4; j++) {
                float2 rv = *(const float2*)(res + ro + ncol[j]);
                float vx = acc[i][j][2 * half]     + bc[j][0] + rv.x;
                float vy = acc[i][j][2 * half + 1] + bc[j][1] + rv.y;
                acc[i][j][2 * half] = vx; acc[i][j][2 * half + 1] = vy;
                s += vx + vy; s2 += vx * vx + vy * vy;
            }
            s  += __shfl_xor_sync(0xffffffffu, s, 1);
            s  += __shfl_xor_sync(0xffffffffu, s, 2);
            s2 += __shfl_xor_sync(0xffffffffu, s2, 1);
            s2 += __shfl_xor_sync(0xffffffffu, s2, 2);
            if (t == 0) { red[0][wn][rl] = s; red[1][wn][rl] = s2; }
        }
    }
    __syncthreads();
    #pragma unroll
    for (int i = 0; i < 4; i++) {
        #pragma unroll
        for (int half = 0; half < 2; half++) {
            int rl = wm * 64 + i * 16 + g + 8 * half;
            float s  = red[0][0][rl] + red[0][1][rl] + red[0][2][rl] + red[0][3][rl];
            float s2 = red[1][0][rl] + red[1][1][rl] + red[1][2][rl] + red[1][3][rl];
            float mu   = s  * (1.f / 128.f);
            float var  = s2 * (1.f / 128.f) - mu * mu;
            float rstd = rsqrtf(var + 1e-5f);
            size_t ro  = (size_t)(m0 + rl) * N;
            size_t ro2 = (size_t)(m0 + rl) * 64;
            #pragma unroll
            for (int j = 0; j < 4; j++) {
                float vx = acc[i][j][2 * half];
                float vy = acc[i][j][2 * half + 1];
                *(float2*)(C + ro + ncol[j]) = make_float2(vx, vy);
                float hx = (vx - mu) * rstd * gc[j][0] + btc[j][0] + zc[j][0];
                float hy = (vy - mu) * rstd * gc[j][1] + btc[j][1] + zc[j][1];
                C2h[ro2 + (ncol[j] >> 1)] = pack_h2(hx, hy);
            }
        }
    }
}

// ---------------------------------------------------------------------------
// Barrier-free flash attention + LePE, fp16 mma, 3 CTAs/SM (proven R14).
// ---------------------------------------------------------------------------
#define QP 520
#define VPH 24
#define OFF_QH 0
#define OFF_KH (8*QP)
#define OFF_VH (16*QP)
#define OFF_W  (OFF_VH + 256*VPH)
#define OFF_B  (OFF_W + 144)
#define ATTN_SMEM_WORDS (OFF_B + 16)

__device__ __forceinline__ int tok_to_l(int n, int br, int wn) {
    if (br == 0) { int h = n >> 3, w = n & 7; return h * 64 + wn * 8 + w; }
    return wn * 512 + n;
}

__global__ void __launch_bounds__(256, 3) attn_kernel(
        const float* __restrict__ lepe_w0, const float* __restrict__ lepe_b0,
        const float* __restrict__ lepe_w1, const float* __restrict__ lepe_b1) {
    extern __shared__ uint32_t smw[];
    uint32_t* Qh  = smw + OFF_QH;
    uint32_t* Kh  = smw + OFF_KH;
    uint32_t* Vh  = smw + OFF_VH;
    float*    wsm = (float*)(smw + OFF_W);
    float*    bsm = (float*)(smw + OFF_B);

    int wglob = blockIdx.x;
    int hd    = blockIdx.y;
    int br    = blockIdx.z;
    int b  = wglob >> 3;
    int wn = wglob & 7;
    int cb = br * 64 + hd * 16;
    int cw = cb >> 1;
    int tid  = threadIdx.x;
    int warp = tid >> 5, lane = tid & 31;
    int g = lane >> 2, t = lane & 3;

    {
        int tp = tid;
        int t0 = tp * 2, t1 = t0 + 1;
        int l0 = tok_to_l(t0, br, wn), l1 = tok_to_l(t1, br, wn);
        const uint32_t* p0 = g_qkvh + (size_t)(b * L_DIM + l0) * 192 + cw;
        const uint32_t* p1 = g_qkvh + (size_t)(b * L_DIM + l1) * 192 + cw;
        uint4 qa0 = *(const uint4*)(p0);       uint4 qa1 = *(const uint4*)(p0 + 4);
        uint4 qb0 = *(const uint4*)(p1);       uint4 qb1 = *(const uint4*)(p1 + 4);
        Qh[0*QP+t0]=qa0.x; Qh[1*QP+t0]=qa0.y; Qh[2*QP+t0]=qa0.z; Qh[3*QP+t0]=qa0.w;
        Qh[4*QP+t0]=qa1.x; Qh[5*QP+t0]=qa1.y; Qh[6*QP+t0]=qa1.z; Qh[7*QP+t0]=qa1.w;
        Qh[0*QP+t1]=qb0.x; Qh[1*QP+t1]=qb0.y; Qh[2*QP+t1]=qb0.z; Qh[3*QP+t1]=qb0.w;
        Qh[4*QP+t1]=qb1.x; Qh[5*QP+t1]=qb1.y; Qh[6*QP+t1]=qb1.z; Qh[7*QP+t1]=qb1.w;
        uint4 ka0 = *(const uint4*)(p0 + 64);  uint4 ka1 = *(const uint4*)(p0 + 68);
        uint4 kb0 = *(const uint4*)(p1 + 64);  uint4 kb1 = *(const uint4*)(p1 + 68);
        Kh[0*QP+t0]=ka0.x; Kh[1*QP+t0]=ka0.y; Kh[2*QP+t0]=ka0.z; Kh[3*QP+t0]=ka0.w;
        Kh[4*QP+t0]=ka1.x; Kh[5*QP+t0]=ka1.y; Kh[6*QP+t0]=ka1.z; Kh[7*QP+t0]=ka1.w;
        Kh[0*QP+t1]=kb0.x; Kh[1*QP+t1]=kb0.y; Kh[2*QP+t1]=kb0.z; Kh[3*QP+t1]=kb0.w;
        Kh[4*QP+t1]=kb1.x; Kh[5*QP+t1]=kb1.y; Kh[6*QP+t1]=kb1.z; Kh[7*QP+t1]=kb1.w;
        uint4 va0 = *(const uint4*)(p0 + 128); uint4 va1 = *(const uint4*)(p0 + 132);
        uint4 vb0 = *(const uint4*)(p1 + 128); uint4 vb1 = *(const uint4*)(p1 + 132);
        uint32_t wa[8] = {va0.x, va0.y, va0.z, va0.w, va1.x, va1.y, va1.z, va1.w};
        uint32_t wb[8] = {vb0.x, vb0.y, vb0.z, vb0.w, vb1.x, vb1.y, vb1.z, vb1.w};
        uint32_t* vr = Vh + tp * VPH;
        #pragma unroll
        for (int i = 0; i < 8; i++) {
            vr[2*i]     = __byte_perm(wa[i], wb[i], 0x5410);
            vr[2*i + 1] = __byte_perm(wa[i], wb[i], 0x7632);
        }
        vr[16] = pack_h2(1.f, 1.f);
        #pragma unroll
        for (int d = 17; d < 24; d++) vr[d] = 0u;
    }
    const float* lw = br ? lepe_w1 : lepe_w0;
    const float* lb = br ? lepe_b1 : lepe_b0;
    if (tid < 144) wsm[tid] = lw[hd * 16 * 9 + tid] * INV_SC;
    if (tid < 16)  bsm[tid] = lb[hd * 16 + tid];
    __syncthreads();

    const int HS = br ? 8 : 64;
    const int WS = br ? 64 : 8;

    #pragma unroll 1
    for (int pass = 0; pass < 4; pass++) {
        int qb = pass * 128 + warp * 16;

        uint32_t af[4];
        af[0] = Qh[t * QP + qb + g];
        af[1] = Qh[t * QP + qb + g + 8];
        af[2] = Qh[(t + 4) * QP + qb + g];
        af[3] = Qh[(t + 4) * QP + qb + g + 8];

        float m0 = -1e30f, m1 = -1e30f;
        float oacc[3][4];
        #pragma unroll
        for (int j = 0; j < 3; j++) {
            oacc[j][0] = 0.f; oacc[j][1] = 0.f;
            oacc[j][2] = 0.f; oacc[j][3] = 0.f;
        }

        #pragma unroll 1
        for (int c = 0; c < 8; c++) {
            int kb = c * 64;
            float sacc[8][4];
            #pragma unroll
            for (int j = 0; j < 8; j++) {
                sacc[j][0] = 0.f; sacc[j][1] = 0.f;
                sacc[j][2] = 0.f; sacc[j][3] = 0.f;
                uint32_t bf[2];
                bf[0] = Kh[t * QP + kb + j * 8 + g];
                bf[1] = Kh[(t + 4) * QP + kb + j * 8 + g];
                mma16n8k16(sacc[j], af, bf);
            }
            float mx0 = sacc[0][0], mx1 = sacc[0][2];
            #pragma unroll
            for (int j = 0; j < 8; j++) {
                mx0 = fmaxf(mx0, fmaxf(sacc[j][0], sacc[j][1]));
                mx1 = fmaxf(mx1, fmaxf(sacc[j][2], sacc[j][3]));
            }
            mx0 = fmaxf(mx0, __shfl_xor_sync(0xffffffffu, mx0, 1));
            mx0 = fmaxf(mx0, __shfl_xor_sync(0xffffffffu, mx0, 2));
            mx1 = fmaxf(mx1, __shfl_xor_sync(0xffffffffu, mx1, 1));
            mx1 = fmaxf(mx1, __shfl_xor_sync(0xffffffffu, mx1, 2));
            float mn0 = fmaxf(m0, mx0), mn1 = fmaxf(m1, mx1);
            float a0 = fast_ex2(m0 - mn0), a1 = fast_ex2(m1 - mn1);
            m0 = mn0; m1 = mn1;
            #pragma unroll
            for (int j = 0; j < 3; j++) {
                oacc[j][0] *= a0; oacc[j][1] *= a0;
                oacc[j][2] *= a1; oacc[j][3] *= a1;
            }
            #pragma unroll
            for (int ks = 0; ks < 4; ks++) {
                uint32_t pf[4];
                pf[0] = ex2_h2(pack_h2(sacc[2*ks][0]   - m0, sacc[2*ks][1]   - m0));
                pf[1] = ex2_h2(pack_h2(sacc[2*ks][2]   - m1, sacc[2*ks][3]   - m1));
                pf[2] = ex2_h2(pack_h2(sacc[2*ks+1][0] - m0, sacc[2*ks+1][1] - m0));
                pf[3] = ex2_h2(pack_h2(sacc[2*ks+1][2] - m1, sacc[2*ks+1][3] - m1));
                int kh = c * 32 + ks * 8;
                #pragma unroll
                for (int j = 0; j < 3; j++) {
                    uint32_t bf[2];
                    bf[0] = Vh[(kh + t) * VPH + j * 8 + g];
                    bf[1] = Vh[(kh + t + 4) * VPH + j * 8 + g];
                    mma16n8k16(oacc[j], pf, bf);
                }
            }
        }

        float l0 = __shfl_sync(0xffffffffu, oacc[2][0], lane & 28);
        float l1 = __shfl_sync(0xffffffffu, oacc[2][2], lane & 28);
        float inv0 = 1.f / l0, inv1 = 1.f / l1;

        #pragma unroll
        for (int half = 0; half < 2; half++) {
            int n = qb + g + 8 * half;
            int hq = n / WS, wq = n % WS;
            float inv = half ? inv1 : inv0;
            int l = tok_to_l(n, br, wn);
            uint32_t* orow = g_atth + (size_t)(b * L_DIM + l) * 64 + cw;
            #pragma unroll
            for (int j = 0; j < 2; j++) {
                int d0 = j * 8 + 2 * t;
                float lp0 = bsm[d0], lp1 = bsm[d0 + 1];
                #pragma unroll
                for (int ky = 0; ky < 3; ky++) {
                    int hh = hq + ky - 1;
                    if (hh < 0 || hh >= HS) continue;
                    #pragma unroll
                    for (int kx = 0; kx < 3; kx++) {
                        int ww = wq + kx - 1;
                        if (ww < 0 || ww >= WS) continue;
                        uint32_t u = Qh[(j * 4 + t) * QP + hh * WS + ww];
                        float2 qf = __half22float2(*(__half2*)&u);
                        lp0 = fmaf(wsm[d0 * 9 + ky * 3 + kx], qf.x, lp0);
                        lp1 = fmaf(wsm[(d0 + 1) * 9 + ky * 3 + kx], qf.y, lp1);
                    }
                }
                float v0 = oacc[j][2 * half]     * inv + lp0;
                float v1 = oacc[j][2 * half + 1] * inv + lp1;
                orow[d0 >> 1] = pack_h2(v0, v1);
            }
        }
    }
}

// ---------------------------------------------------------------------------
extern "C" void kernel_launch(void* const* d_in, const int* in_sizes, int n_in,
                              void* d_out, int out_size) {
    const float* x       = (const float*)d_in[0];
    const float* z       = (const float*)d_in[1];
    const float* ln1_g   = (const float*)d_in[2];
    const float* ln1_b   = (const float*)d_in[3];
    const float* ln2_g   = (const float*)d_in[4];
    const float* ln2_b   = (const float*)d_in[5];
    const float* Wz1     = (const float*)d_in[6];
    const float* Wz2     = (const float*)d_in[7];
    const float* Wqkv    = (const float*)d_in[8];
    const float* Wproj   = (const float*)d_in[9];
    const float* bproj   = (const float*)d_in[10];
    const float* lepe_w0 = (const float*)d_in[11];
    const float* lepe_b0 = (const float*)d_in[12];
    const float* lepe_w1 = (const float*)d_in[13];
    const float* lepe_b1 = (const float*)d_in[14];
    const float* W1      = (const float*)d_in[15];
    const float* b1      = (const float*)d_in[16];
    const float* W2      = (const float*)d_in[17];
    const float* b2      = (const float*)d_in[18];
    float* out = (float*)d_out;

    float*    p_xf;    cudaGetSymbolAddress((void**)&p_xf,    g_xf);
    float*    p_xf2;   cudaGetSymbolAddress((void**)&p_xf2,   g_xf2);
    uint32_t* p_h1h;   cudaGetSymbolAddress((void**)&p_h1h,   g_h1h);
    uint32_t* p_qkvh;  cudaGetSymbolAddress((void**)&p_qkvh,  g_qkvh);
    uint32_t* p_atth;  cudaGetSymbolAddress((void**)&p_atth,  g_atth);
    uint32_t* p_h2h;   cudaGetSymbolAddress((void**)&p_h2h,   g_h2h);
    uint32_t* p_midh;  cudaGetSymbolAddress((void**)&p_midh,  g_midh);
    uint32_t* p_wqkvh; cudaGetSymbolAddress((void**)&p_wqkvh, g_wqkvh);
    uint32_t* p_wprojh;cudaGetSymbolAddress((void**)&p_wprojh,g_wprojh);
    uint32_t* p_w1h;   cudaGetSymbolAddress((void**)&p_w1h,   g_w1h);
    uint32_t* p_w2h;   cudaGetSymbolAddress((void**)&p_w2h,   g_w2h);

    const int attn_smem = ATTN_SMEM_WORDS * (int)sizeof(uint32_t);
    cudaFuncSetAttribute(attn_kernel, cudaFuncAttributeMaxDynamicSharedMemorySize, attn_smem);

    // 1) z projections + weight fp16 conversion
    prep_kernel<<<56, 256>>>(z, Wz1, Wz2, Wqkv, Wproj, W1, W2);
    // 2) transpose + LN1 (+z1): xf fp32, h1 fp16
    ln1_kernel<<<dim3(128, 8), 256>>>(x, ln1_g, ln1_b);
    // 3) qkv = h1 @ Wqkv^T  -> fp16, Q pre-scaled
    gemm_h<1><<<dim3(QKV_N / 128, M_ROWS / 128), 256>>>(
        p_h1h, p_wqkvh, nullptr, nullptr, p_qkvh, M_ROWS, QKV_N, C_DIM, 0, 1);
    // 4) windowed attention + LePE -> att fp16
    attn_kernel<<<dim3(64, 4, 2), 256, attn_smem>>>(lepe_w0, lepe_b0, lepe_w1, lepe_b1);
    // 5) xf2 = xf + att @ Wproj^T + bproj (fp32);  h2 = LN2(xf2)+z2 (fp16)
    gemm_ln_kernel<<<dim3(1, M_ROWS / 128), 256>>>(
        p_atth, p_wprojh, bproj, p_xf, p_xf2, p_h2h, ln2_g, ln2_b, M_ROWS, C_DIM);
    // 6) mid = gelu(h2 @ W1^T + b1) -> fp16
    gemm_h<1><<<dim3(HID / 128, M_ROWS / 128), 256>>>(
        p_h2h, p_w1h, b1, nullptr, p_midh, M_ROWS, HID, C_DIM, 1, 0);
    // 7) out = T(xf2 + mid @ W2^T + b2)  -> (B,C,H,W), fused transpose
    gemm_trans_kernel<<<dim3(1, M_ROWS / 128), 256>>>(
        p_midh, p_w2h, b2, p_xf2, out, M_ROWS, HID);
}

// round 17
// speedup vs baseline: 1.5932x; 1.0074x over previous
#include <cuda_runtime.h>
#include <cuda_bf16.h>
#include <cuda_fp16.h>
#include <cstdint>
#include <math.h>

// ---------------------------------------------------------------------------
// Problem constants
// ---------------------------------------------------------------------------
#define M_ROWS   32768
#define C_DIM    128
#define L_DIM    4096
#define B_DIM    8
#define HID      512
#define QKV_N    384
#define ZC       512

// ---------------------------------------------------------------------------
// Scratch buffers.  fp16 tensors stored as packed half2 words (uint32).
// ---------------------------------------------------------------------------
__device__ __align__(16) float    g_xf  [M_ROWS * C_DIM];
__device__ __align__(16) float    g_xf2 [M_ROWS * C_DIM];
__device__ __align__(16) uint32_t g_h1h [M_ROWS * (C_DIM/2)];
__device__ __align__(16) uint32_t g_qkvh[M_ROWS * (QKV_N/2)];
__device__ __align__(16) uint32_t g_atth[M_ROWS * (C_DIM/2)];
__device__ __align__(16) uint32_t g_h2h [M_ROWS * (C_DIM/2)];
__device__ __align__(16) uint32_t g_midh[M_ROWS * (HID/2)];
__device__ __align__(16) float    g_z1  [B_DIM * C_DIM];
__device__ __align__(16) float    g_z2  [B_DIM * C_DIM];
// fp16 weights (packed half2 along K)
__device__ __align__(16) uint32_t g_wqkvh[QKV_N * (C_DIM/2)];
__device__ __align__(16) uint32_t g_wprojh[C_DIM * (C_DIM/2)];
__device__ __align__(16) uint32_t g_w1h  [HID * (C_DIM/2)];
__device__ __align__(16) uint32_t g_w2h  [C_DIM * (HID/2)];

#define SOFTMAX_SC 0.36067376022224085f   // 0.25 * log2(e)
#define INV_SC     2.7725887222397811f    // 1 / SOFTMAX_SC = 4 ln 2

// ---------------------------------------------------------------------------
// helpers
// ---------------------------------------------------------------------------
__device__ __forceinline__ uint32_t pack_h2(float lo, float hi) {
    uint32_t u;
    asm("cvt.rn.f16x2.f32 %0, %1, %2;" : "=r"(u) : "f"(hi), "f"(lo));
    return u;
}
__device__ __forceinline__ uint32_t ex2_h2(uint32_t h2) {
    uint32_t r;
    asm("ex2.approx.f16x2 %0, %1;" : "=r"(r) : "r"(h2));
    return r;
}
__device__ __forceinline__ float fast_ex2(float x) {
    float y;
    asm("ex2.approx.ftz.f32 %0, %1;" : "=f"(y) : "f"(x));
    return y;
}
__device__ __forceinline__ float gelu_f(float v) {
    return 0.5f * v * (1.f + erff(v * 0.70710678118654752f));
}
__device__ __forceinline__ void mma16n8k16(float* d, const uint32_t* a,
                                           const uint32_t* b) {
    asm("mma.sync.aligned.m16n8k16.row.col.f32.f16.f16.f32 "
        "{%0,%1,%2,%3}, {%4,%5,%6,%7}, {%8,%9}, {%0,%1,%2,%3};"
        : "+f"(d[0]), "+f"(d[1]), "+f"(d[2]), "+f"(d[3])
        : "r"(a[0]), "r"(a[1]), "r"(a[2]), "r"(a[3]), "r"(b[0]), "r"(b[1]));
}

// ---------------------------------------------------------------------------
// prep: z projections (blocks 0-7) + weight fp16 conversion (blocks 8-55)
// ---------------------------------------------------------------------------
__global__ void prep_kernel(const float* __restrict__ z,
                            const float* __restrict__ Wz1,
                            const float* __restrict__ Wz2,
                            const float* __restrict__ Wqkv,
                            const float* __restrict__ Wproj,
                            const float* __restrict__ W1,
                            const float* __restrict__ W2) {
    if (blockIdx.x < 8) {
        int o = blockIdx.x * 256 + threadIdx.x;
        int which = o >> 10;
        int b = (o >> 7) & 7;
        int c = o & 127;
        const float* W = (which ? Wz2 : Wz1) + c * ZC;
        const float* zb = z + b * ZC;
        float s = 0.f;
        #pragma unroll 8
        for (int k = 0; k < ZC; k++) s += zb[k] * W[k];
        (which ? g_z2 : g_z1)[b * C_DIM + c] = s;
        return;
    }
    int idx = (blockIdx.x - 8) * 2048 + threadIdx.x * 8;
    const float* src; uint32_t* dst; int base;
    if (idx < 24576)      { src = Wqkv;  dst = g_wqkvh;  base = idx; }
    else if (idx < 32768) { src = Wproj; dst = g_wprojh; base = idx - 24576; }
    else if (idx < 65536) { src = W1;    dst = g_w1h;    base = idx - 32768; }
    else                  { src = W2;    dst = g_w2h;    base = idx - 65536; }
    const float* s = src + (size_t)base * 2;
    uint32_t w[8];
    #pragma unroll
    for (int i = 0; i < 4; i++) {
        float4 v = ((const float4*)s)[i];
        w[2*i]   = pack_h2(v.x, v.y);
        w[2*i+1] = pack_h2(v.z, v.w);
    }
    uint4 o0 = {w[0], w[1], w[2], w[3]};
    uint4 o1 = {w[4], w[5], w[6], w[7]};
    *(uint4*)(dst + base)     = o0;
    *(uint4*)(dst + base + 4) = o1;
}

// ---------------------------------------------------------------------------
// Transpose x -> xf (fp32) and h1 = LN(xf)+z1 packed fp16.
// ---------------------------------------------------------------------------
__global__ void __launch_bounds__(256) ln1_kernel(const float* __restrict__ x,
                                                  const float* __restrict__ gamma,
                                                  const float* __restrict__ beta) {
    __shared__ float sm[128][33];
    int b  = blockIdx.y;
    int l0 = blockIdx.x * 32;
    int tid = threadIdx.x;
    const float* xb = x + (size_t)b * C_DIM * L_DIM;
    #pragma unroll
    for (int r = 0; r < 16; r++) {
        int c = r * 8 + (tid >> 5);
        int j = tid & 31;
        sm[c][j] = xb[(size_t)c * L_DIM + l0 + j];
    }
    __syncthreads();
    int warp = tid >> 5, lane = tid & 31;
    #pragma unroll
    for (int rr = 0; rr < 4; rr++) {
        int j = warp + rr * 8;
        float v[4];
        v[0] = sm[2 * lane][j];
        v[1] = sm[2 * lane + 1][j];
        v[2] = sm[64 + 2 * lane][j];
        v[3] = sm[65 + 2 * lane][j];
        float s = v[0] + v[1] + v[2] + v[3];
        float s2 = v[0]*v[0] + v[1]*v[1] + v[2]*v[2] + v[3]*v[3];
        #pragma unroll
        for (int o = 16; o; o >>= 1) {
            s  += __shfl_xor_sync(0xffffffffu, s,  o);
            s2 += __shfl_xor_sync(0xffffffffu, s2, o);
        }
        float mu   = s  * (1.f / 128.f);
        float var  = s2 * (1.f / 128.f) - mu * mu;
        float rstd = rsqrtf(var + 1e-5f);
        int l = l0 + j;
        size_t row = (size_t)b * L_DIM + l;
        float* xfr = g_xf + row * C_DIM;
        *(float2*)(xfr + 2 * lane)      = make_float2(v[0], v[1]);
        *(float2*)(xfr + 64 + 2 * lane) = make_float2(v[2], v[3]);
        const float* z1b = g_z1 + b * C_DIM;
        float h[4];
        #pragma unroll
        for (int u = 0; u < 4; u++) {
            int c = (u < 2) ? (2 * lane + u) : (62 + 2 * lane + u);
            h[u] = (v[u] - mu) * rstd * gamma[c] + beta[c] + z1b[c];
        }
        uint32_t* hr = g_h1h + row * 64;
        hr[lane]      = pack_h2(h[0], h[1]);
        hr[32 + lane] = pack_h2(h[2], h[3]);
    }
}

// ---------------------------------------------------------------------------
// Lean tensor-core GEMM, BK=32, both operands fp16 words, [row][RS] smem.
// ONE sync per slab (double-buffered proof in header comment of round log);
// prefetch issued BEFORE the barrier so gmem latency overlaps it.
// CH=0: C fp32 with optional res;  CH=1: C fp16 words, optional qscale.
// ---------------------------------------------------------------------------
#define RS 20

template<int CH>
__global__ void __launch_bounds__(256) gemm_h(
        const uint32_t* __restrict__ A, const uint32_t* __restrict__ Wh,
        const float* __restrict__ bias, const float* __restrict__ res,
        void* __restrict__ Cv, int M, int N, int K, int act, int qsc) {
    __shared__ uint32_t As[2][128 * RS];
    __shared__ uint32_t Bs[2][128 * RS];
    int tid  = threadIdx.x;
    int warp = tid >> 5, lane = tid & 31;
    int wm = warp >> 2;
    int wn = warp & 3;
    int t = lane & 3, g = lane >> 2;
    int m0 = blockIdx.y * 128, n0 = blockIdx.x * 128;
    int K2 = K >> 1;

    float acc[4][4][4];
    #pragma unroll
    for (int i = 0; i < 4; i++)
        #pragma unroll
        for (int j = 0; j < 4; j++)
            #pragma unroll
            for (int r = 0; r < 4; r++) acc[i][j][r] = 0.f;

    int arow = tid >> 1;
    int aoff = (tid & 1) << 3;
    uint4 pa[2], pb[2];
    {
        const uint32_t* ap = A  + (size_t)(m0 + arow) * K2 + aoff;
        const uint32_t* bp = Wh + (size_t)(n0 + arow) * K2 + aoff;
        pa[0] = *(const uint4*)ap;     pa[1] = *(const uint4*)(ap + 4);
        pb[0] = *(const uint4*)bp;     pb[1] = *(const uint4*)(bp + 4);
    }

    int slabs = K >> 5;
    for (int s = 0; s < slabs; s++) {
        uint32_t* Ab = As[s & 1];
        uint32_t* Bb = Bs[s & 1];
        {
            uint4* da = (uint4*)&Ab[arow * RS + aoff];
            da[0] = pa[0]; da[1] = pa[1];
            uint4* db = (uint4*)&Bb[arow * RS + aoff];
            db[0] = pb[0]; db[1] = pb[1];
        }
        // prefetch next slab BEFORE the barrier (overlaps gmem latency)
        if (s + 1 < slabs) {
            const uint32_t* ap = A  + (size_t)(m0 + arow) * K2 + (s + 1) * 16 + aoff;
            const uint32_t* bp = Wh + (size_t)(n0 + arow) * K2 + (s + 1) * 16 + aoff;
            pa[0] = *(const uint4*)ap;  pa[1] = *(const uint4*)(ap + 4);
            pb[0] = *(const uint4*)bp;  pb[1] = *(const uint4*)(bp + 4);
        }
        __syncthreads();
        #pragma unroll
        for (int ks = 0; ks < 2; ks++) {
            uint32_t af[4][4], bf[4][2];
            #pragma unroll
            for (int i = 0; i < 4; i++) {
                const uint32_t* p = Ab + (wm * 64 + i * 16 + g) * RS + ks * 8 + t;
                af[i][0] = p[0];
                af[i][1] = p[8 * RS];
                af[i][2] = p[4];
                af[i][3] = p[8 * RS + 4];
            }
            #pragma unroll
            for (int j = 0; j < 4; j++) {
                const uint32_t* p = Bb + (wn * 32 + j * 8 + g) * RS + ks * 8 + t;
                bf[j][0] = p[0];
                bf[j][1] = p[4];
            }
            #pragma unroll
            for (int i = 0; i < 4; i++)
                #pragma unroll
                for (int j = 0; j < 4; j++)
                    mma16n8k16(acc[i][j], af[i], bf[j]);
        }
        // no trailing sync: next store targets the other buffer; reads of
        // that buffer happened before this iteration's barrier.
    }

    if (CH == 0) {
        float* C = (float*)Cv;
        #pragma unroll
        for (int i = 0; i < 4; i++) {
            int mr = m0 + wm * 64 + i * 16 + g;
            #pragma unroll
            for (int half = 0; half < 2; half++) {
                int m = mr + 8 * half;
                size_t ro = (size_t)m * N;
                #pragma unroll
                for (int j = 0; j < 4; j++) {
                    int n = n0 + wn * 32 + j * 8 + 2 * t;
                    float vx = acc[i][j][2 * half];
                    float vy = acc[i][j][2 * half + 1];
                    if (bias) { vx += bias[n]; vy += bias[n + 1]; }
                    if (res) {
                        float2 rv = *(const float2*)(res + ro + n);
                        vx += rv.x; vy += rv.y;
                    }
                    if (act) { vx = gelu_f(vx); vy = gelu_f(vy); }
                    *(float2*)(C + ro + n) = make_float2(vx, vy);
                }
            }
        }
    } else {
        uint32_t* Ch = (uint32_t*)Cv;
        int N2 = N >> 1;
        #pragma unroll
        for (int i = 0; i < 4; i++) {
            int mr = m0 + wm * 64 + i * 16 + g;
            #pragma unroll
            for (int half = 0; half < 2; half++) {
                int m = mr + 8 * half;
                size_t ro = (size_t)m * N2;
                #pragma unroll
                for (int j = 0; j < 4; j++) {
                    int n = n0 + wn * 32 + j * 8 + 2 * t;
                    float vx = acc[i][j][2 * half];
                    float vy = acc[i][j][2 * half + 1];
                    if (bias) { vx += bias[n]; vy += bias[n + 1]; }
                    if (act) { vx = gelu_f(vx); vy = gelu_f(vy); }
                    if (qsc && n < 128) { vx *= SOFTMAX_SC; vy *= SOFTMAX_SC; }
                    Ch[ro + (n >> 1)] = pack_h2(vx, vy);
                }
            }
        }
    }
}

// ---------------------------------------------------------------------------
// mlp2 GEMM with fused output transpose (reused GEMM smem, no extra shared).
// ---------------------------------------------------------------------------
__global__ void __launch_bounds__(256) gemm_trans_kernel(
        const uint32_t* __restrict__ A, const uint32_t* __restrict__ Wh,
        const float* __restrict__ bias, const float* __restrict__ res,
        float* __restrict__ Cout, int M, int K) {
    __shared__ __align__(16) union {
        uint32_t buf[4][128 * RS];
        float    ts[64 * 132];
    } smu;
    const int N = 128;
    int tid  = threadIdx.x;
    int warp = tid >> 5, lane = tid & 31;
    int wm = warp >> 2;
    int wn = warp & 3;
    int t = lane & 3, g = lane >> 2;
    int m0 = blockIdx.y * 128;
    int K2 = K >> 1;

    float acc[4][4][4];
    #pragma unroll
    for (int i = 0; i < 4; i++)
        #pragma unroll
        for (int j = 0; j < 4; j++)
            #pragma unroll
            for (int r = 0; r < 4; r++) acc[i][j][r] = 0.f;

    int arow = tid >> 1;
    int aoff = (tid & 1) << 3;
    uint4 pa[2], pb[2];
    {
        const uint32_t* ap = A  + (size_t)(m0 + arow) * K2 + aoff;
        const uint32_t* bp = Wh + (size_t)arow * K2 + aoff;
        pa[0] = *(const uint4*)ap;     pa[1] = *(const uint4*)(ap + 4);
        pb[0] = *(const uint4*)bp;     pb[1] = *(const uint4*)(bp + 4);
    }

    int slabs = K >> 5;
    for (int s = 0; s < slabs; s++) {
        uint32_t* Ab = smu.buf[s & 1];
        uint32_t* Bb = smu.buf[2 + (s & 1)];
        {
            uint4* da = (uint4*)&Ab[arow * RS + aoff];
            da[0] = pa[0]; da[1] = pa[1];
            uint4* db = (uint4*)&Bb[arow * RS + aoff];
            db[0] = pb[0]; db[1] = pb[1];
        }
        if (s + 1 < slabs) {
            const uint32_t* ap = A  + (size_t)(m0 + arow) * K2 + (s + 1) * 16 + aoff;
            const uint32_t* bp = Wh + (size_t)arow * K2 + (s + 1) * 16 + aoff;
            pa[0] = *(const uint4*)ap;  pa[1] = *(const uint4*)(ap + 4);
            pb[0] = *(const uint4*)bp;  pb[1] = *(const uint4*)(bp + 4);
        }
        __syncthreads();
        #pragma unroll
        for (int ks = 0; ks < 2; ks++) {
            uint32_t af[4][4], bf[4][2];
            #pragma unroll
            for (int i = 0; i < 4; i++) {
                const uint32_t* p = Ab + (wm * 64 + i * 16 + g) * RS + ks * 8 + t;
                af[i][0] = p[0];
                af[i][1] = p[8 * RS];
                af[i][2] = p[4];
                af[i][3] = p[8 * RS + 4];
            }
            #pragma unroll
            for (int j = 0; j < 4; j++) {
                const uint32_t* p = Bb + (wn * 32 + j * 8 + g) * RS + ks * 8 + t;
                bf[j][0] = p[0];
                bf[j][1] = p[4];
            }
            #pragma unroll
            for (int i = 0; i < 4; i++)
                #pragma unroll
                for (int j = 0; j < 4; j++)
                    mma16n8k16(acc[i][j], af[i], bf[j]);
        }
    }
    __syncthreads();   // all frag reads done before union reuse below

    int b  = m0 >> 12;
    int l0 = m0 & (L_DIM - 1);
    #pragma unroll
    for (int cc = 0; cc < 2; cc++) {
        if ((wn >> 1) == cc) {
            #pragma unroll
            for (int i = 0; i < 4; i++) {
                #pragma unroll
                for (int half = 0; half < 2; half++) {
                    int ml = wm * 64 + i * 16 + g + 8 * half;
                    size_t ro = (size_t)(m0 + ml) * N;
                    #pragma unroll
                    for (int j = 0; j < 4; j++) {
                        int n = wn * 32 + j * 8 + 2 * t;
                        float vx = acc[i][j][2 * half]     + bias[n];
                        float vy = acc[i][j][2 * half + 1] + bias[n + 1];
                        float2 rv = *(const float2*)(res + ro + n);
                        vx += rv.x; vy += rv.y;
                        int nn = n - cc * 64;
                        smu.ts[nn * 132 + ml]       = vx;
                        smu.ts[(nn + 1) * 132 + ml] = vy;
                    }
                }
            }
        }
        __syncthreads();
        #pragma unroll
        for (int it = 0; it < 8; it++) {
            int cl = warp * 8 + it;
            int c  = cc * 64 + cl;
            float4 v = *(const float4*)&smu.ts[cl * 132 + lane * 4];
            *(float4*)(Cout + ((size_t)b * C_DIM + c) * L_DIM + l0 + lane * 4) = v;
        }
        if (cc == 0) __syncthreads();
    }
}

// ---------------------------------------------------------------------------
// proj GEMM with fused LN2 (BK=32, fp16 weights).  N == 128, gridDim.x == 1.
// ---------------------------------------------------------------------------
__global__ void __launch_bounds__(256) gemm_ln_kernel(
        const uint32_t* __restrict__ A, const uint32_t* __restrict__ Wh,
        const float* __restrict__ bias, const float* __restrict__ res,
        float* __restrict__ C, uint32_t* __restrict__ C2h,
        const float* __restrict__ gamma, const float* __restrict__ beta,
        int M, int K) {
    __shared__ uint32_t As[2][128 * RS];
    __shared__ uint32_t Bs[2][128 * RS];
    __shared__ float red[2][4][128];
    const int N = 128;
    int tid  = threadIdx.x;
    int warp = tid >> 5, lane = tid & 31;
    int wm = warp >> 2;
    int wn = warp & 3;
    int t = lane & 3, g = lane >> 2;
    int m0 = blockIdx.y * 128;
    int K2 = K >> 1;

    float acc[4][4][4];
    #pragma unroll
    for (int i = 0; i < 4; i++)
        #pragma unroll
        for (int j = 0; j < 4; j++)
            #pragma unroll
            for (int r = 0; r < 4; r++) acc[i][j][r] = 0.f;

    int arow = tid >> 1;
    int aoff = (tid & 1) << 3;
    uint4 pa[2], pb[2];
    {
        const uint32_t* ap = A  + (size_t)(m0 + arow) * K2 + aoff;
        const uint32_t* bp = Wh + (size_t)arow * K2 + aoff;
        pa[0] = *(const uint4*)ap;     pa[1] = *(const uint4*)(ap + 4);
        pb[0] = *(const uint4*)bp;     pb[1] = *(const uint4*)(bp + 4);
    }

    int slabs = K >> 5;
    for (int s = 0; s < slabs; s++) {
        uint32_t* Ab = As[s & 1];
        uint32_t* Bb = Bs[s & 1];
        {
            uint4* da = (uint4*)&Ab[arow * RS + aoff];
            da[0] = pa[0]; da[1] = pa[1];
            uint4* db = (uint4*)&Bb[arow * RS + aoff];
            db[0] = pb[0]; db[1] = pb[1];
        }
        if (s + 1 < slabs) {
            const uint32_t* ap = A  + (size_t)(m0 + arow) * K2 + (s + 1) * 16 + aoff;
            const uint32_t* bp = Wh + (size_t)arow * K2 + (s + 1) * 16 + aoff;
            pa[0] = *(const uint4*)ap;  pa[1] = *(const uint4*)(ap + 4);
            pb[0] = *(const uint4*)bp;  pb[1] = *(const uint4*)(bp + 4);
        }
        __syncthreads();
        #pragma unroll
        for (int ks = 0; ks < 2; ks++) {
            uint32_t af[4][4], bf[4][2];
            #pragma unroll
            for (int i = 0; i < 4; i++) {
                const uint32_t* p = Ab + (wm * 64 + i * 16 + g) * RS + ks * 8 + t;
                af[i][0] = p[0];
                af[i][1] = p[8 * RS];
                af[i][2] = p[4];
                af[i][3] = p[8 * RS + 4];
            }
            #pragma unroll
            for (int j = 0; j < 4; j++) {
                const uint32_t* p = Bb + (wn * 32 + j * 8 + g) * RS + ks * 8 + t;
                bf[j][0] = p[0];
                bf[j][1] = p[4];
            }
            #pragma unroll
            for (int i = 0; i < 4; i++)
                #pragma unroll
                for (int j = 0; j < 4; j++)
                    mma16n8k16(acc[i][j], af[i], bf[j]);
        }
    }

    int ncol[4];
    float bc[4][2], gc[4][2], btc[4][2], zc[4][2];
    int bidx = m0 >> 12;
    #pragma unroll
    for (int j = 0; j < 4; j++) {
        int n = wn * 32 + j * 8 + 2 * t;
        ncol[j] = n;
        bc[j][0]  = bias[n];   bc[j][1]  = bias[n + 1];
        gc[j][0]  = gamma[n];  gc[j][1]  = gamma[n + 1];
        btc[j][0] = beta[n];   btc[j][1] = beta[n + 1];
        zc[j][0]  = g_z2[bidx * C_DIM + n];
        zc[j][1]  = g_z2[bidx * C_DIM + n + 1];
    }
    #pragma unroll
    for (int i = 0; i < 4; i++) {
        #pragma unroll
        for (int half = 0; half < 2; half++) {
            int rl = wm * 64 + i * 16 + g + 8 * half;
            size_t ro = (size_t)(m0 + rl) * N;
            float s = 0.f, s2 = 0.f;
            #pragma unroll
            for (int j = 0; j < 4; j++) {
                float2 rv = *(const float2*)(res + ro + ncol[j]);
                float vx = acc[i][j][2 * half]     + bc[j][0] + rv.x;
                float vy = acc[i][j][2 * half + 1] + bc[j][1] + rv.y;
                acc[i][j][2 * half] = vx; acc[i][j][2 * half + 1] = vy;
                s += vx + vy; s2 += vx * vx + vy * vy;
            }
            s  += __shfl_xor_sync(0xffffffffu, s, 1);
            s  += __shfl_xor_sync(0xffffffffu, s, 2);
            s2 += __shfl_xor_sync(0xffffffffu, s2, 1);
            s2 += __shfl_xor_sync(0xffffffffu, s2, 2);
            if (t == 0) { red[0][wn][rl] = s; red[1][wn][rl] = s2; }
        }
    }
    __syncthreads();
    #pragma unroll
    for (int i = 0; i < 4; i++) {
        #pragma unroll
        for (int half = 0; half < 2; half++) {
            int rl = wm * 64 + i * 16 + g + 8 * half;
            float s  = red[0][0][rl] + red[0][1][rl] + red[0][2][rl] + red[0][3][rl];
            float s2 = red[1][0][rl] + red[1][1][rl] + red[1][2][rl] + red[1][3][rl];
            float mu   = s  * (1.f / 128.f);
            float var  = s2 * (1.f / 128.f) - mu * mu;
            float rstd = rsqrtf(var + 1e-5f);
            size_t ro  = (size_t)(m0 + rl) * N;
            size_t ro2 = (size_t)(m0 + rl) * 64;
            #pragma unroll
            for (int j = 0; j < 4; j++) {
                float vx = acc[i][j][2 * half];
                float vy = acc[i][j][2 * half + 1];
                *(float2*)(C + ro + ncol[j]) = make_float2(vx, vy);
                float hx = (vx - mu) * rstd * gc[j][0] + btc[j][0] + zc[j][0];
                float hy = (vy - mu) * rstd * gc[j][1] + btc[j][1] + zc[j][1];
                C2h[ro2 + (ncol[j] >> 1)] = pack_h2(hx, hy);
            }
        }
    }
}

// ---------------------------------------------------------------------------
// Barrier-free flash attention + LePE, fp16 mma, 3 CTAs/SM (proven).
// ---------------------------------------------------------------------------
#define QP 520
#define VPH 24
#define OFF_QH 0
#define OFF_KH (8*QP)
#define OFF_VH (16*QP)
#define OFF_W  (OFF_VH + 256*VPH)
#define OFF_B  (OFF_W + 144)
#define ATTN_SMEM_WORDS (OFF_B + 16)

__device__ __forceinline__ int tok_to_l(int n, int br, int wn) {
    if (br == 0) { int h = n >> 3, w = n & 7; return h * 64 + wn * 8 + w; }
    return wn * 512 + n;
}

__global__ void __launch_bounds__(256, 3) attn_kernel(
        const float* __restrict__ lepe_w0, const float* __restrict__ lepe_b0,
        const float* __restrict__ lepe_w1, const float* __restrict__ lepe_b1) {
    extern __shared__ uint32_t smw[];
    uint32_t* Qh  = smw + OFF_QH;
    uint32_t* Kh  = smw + OFF_KH;
    uint32_t* Vh  = smw + OFF_VH;
    float*    wsm = (float*)(smw + OFF_W);
    float*    bsm = (float*)(smw + OFF_B);

    int wglob = blockIdx.x;
    int hd    = blockIdx.y;
    int br    = blockIdx.z;
    int b  = wglob >> 3;
    int wn = wglob & 7;
    int cb = br * 64 + hd * 16;
    int cw = cb >> 1;
    int tid  = threadIdx.x;
    int warp = tid >> 5, lane = tid & 31;
    int g = lane >> 2, t = lane & 3;

    {
        int tp = tid;
        int t0 = tp * 2, t1 = t0 + 1;
        int l0 = tok_to_l(t0, br, wn), l1 = tok_to_l(t1, br, wn);
        const uint32_t* p0 = g_qkvh + (size_t)(b * L_DIM + l0) * 192 + cw;
        const uint32_t* p1 = g_qkvh + (size_t)(b * L_DIM + l1) * 192 + cw;
        uint4 qa0 = *(const uint4*)(p0);       uint4 qa1 = *(const uint4*)(p0 + 4);
        uint4 qb0 = *(const uint4*)(p1);       uint4 qb1 = *(const uint4*)(p1 + 4);
        Qh[0*QP+t0]=qa0.x; Qh[1*QP+t0]=qa0.y; Qh[2*QP+t0]=qa0.z; Qh[3*QP+t0]=qa0.w;
        Qh[4*QP+t0]=qa1.x; Qh[5*QP+t0]=qa1.y; Qh[6*QP+t0]=qa1.z; Qh[7*QP+t0]=qa1.w;
        Qh[0*QP+t1]=qb0.x; Qh[1*QP+t1]=qb0.y; Qh[2*QP+t1]=qb0.z; Qh[3*QP+t1]=qb0.w;
        Qh[4*QP+t1]=qb1.x; Qh[5*QP+t1]=qb1.y; Qh[6*QP+t1]=qb1.z; Qh[7*QP+t1]=qb1.w;
        uint4 ka0 = *(const uint4*)(p0 + 64);  uint4 ka1 = *(const uint4*)(p0 + 68);
        uint4 kb0 = *(const uint4*)(p1 + 64);  uint4 kb1 = *(const uint4*)(p1 + 68);
        Kh[0*QP+t0]=ka0.x; Kh[1*QP+t0]=ka0.y; Kh[2*QP+t0]=ka0.z; Kh[3*QP+t0]=ka0.w;
        Kh[4*QP+t0]=ka1.x; Kh[5*QP+t0]=ka1.y; Kh[6*QP+t0]=ka1.z; Kh[7*QP+t0]=ka1.w;
        Kh[0*QP+t1]=kb0.x; Kh[1*QP+t1]=kb0.y; Kh[2*QP+t1]=kb0.z; Kh[3*QP+t1]=kb0.w;
        Kh[4*QP+t1]=kb1.x; Kh[5*QP+t1]=kb1.y; Kh[6*QP+t1]=kb1.z; Kh[7*QP+t1]=kb1.w;
        uint4 va0 = *(const uint4*)(p0 + 128); uint4 va1 = *(const uint4*)(p0 + 132);
        uint4 vb0 = *(const uint4*)(p1 + 128); uint4 vb1 = *(const uint4*)(p1 + 132);
        uint32_t wa[8] = {va0.x, va0.y, va0.z, va0.w, va1.x, va1.y, va1.z, va1.w};
        uint32_t wb[8] = {vb0.x, vb0.y, vb0.z, vb0.w, vb1.x, vb1.y, vb1.z, vb1.w};
        uint32_t* vr = Vh + tp * VPH;
        #pragma unroll
        for (int i = 0; i < 8; i++) {
            vr[2*i]     = __byte_perm(wa[i], wb[i], 0x5410);
            vr[2*i + 1] = __byte_perm(wa[i], wb[i], 0x7632);
        }
        vr[16] = pack_h2(1.f, 1.f);
        #pragma unroll
        for (int d = 17; d < 24; d++) vr[d] = 0u;
    }
    const float* lw = br ? lepe_w1 : lepe_w0;
    const float* lb = br ? lepe_b1 : lepe_b0;
    if (tid < 144) wsm[tid] = lw[hd * 16 * 9 + tid] * INV_SC;
    if (tid < 16)  bsm[tid] = lb[hd * 16 + tid];
    __syncthreads();

    const int HS = br ? 8 : 64;
    const int WS = br ? 64 : 8;

    #pragma unroll 1
    for (int pass = 0; pass < 4; pass++) {
        int qb = pass * 128 + warp * 16;

        uint32_t af[4];
        af[0] = Qh[t * QP + qb + g];
        af[1] = Qh[t * QP + qb + g + 8];
        af[2] = Qh[(t + 4) * QP + qb + g];
        af[3] = Qh[(t + 4) * QP + qb + g + 8];

        float m0 = -1e30f, m1 = -1e30f;
        float oacc[3][4];
        #pragma unroll
        for (int j = 0; j < 3; j++) {
            oacc[j][0] = 0.f; oacc[j][1] = 0.f;
            oacc[j][2] = 0.f; oacc[j][3] = 0.f;
        }

        #pragma unroll 1
        for (int c = 0; c < 8; c++) {
            int kb = c * 64;
            float sacc[8][4];
            #pragma unroll
            for (int j = 0; j < 8; j++) {
                sacc[j][0] = 0.f; sacc[j][1] = 0.f;
                sacc[j][2] = 0.f; sacc[j][3] = 0.f;
                uint32_t bf[2];
                bf[0] = Kh[t * QP + kb + j * 8 + g];
                bf[1] = Kh[(t + 4) * QP + kb + j * 8 + g];
                mma16n8k16(sacc[j], af, bf);
            }
            float mx0 = sacc[0][0], mx1 = sacc[0][2];
            #pragma unroll
            for (int j = 0; j < 8; j++) {
                mx0 = fmaxf(mx0, fmaxf(sacc[j][0], sacc[j][1]));
                mx1 = fmaxf(mx1, fmaxf(sacc[j][2], sacc[j][3]));
            }
            mx0 = fmaxf(mx0, __shfl_xor_sync(0xffffffffu, mx0, 1));
            mx0 = fmaxf(mx0, __shfl_xor_sync(0xffffffffu, mx0, 2));
            mx1 = fmaxf(mx1, __shfl_xor_sync(0xffffffffu, mx1, 1));
            mx1 = fmaxf(mx1, __shfl_xor_sync(0xffffffffu, mx1, 2));
            float mn0 = fmaxf(m0, mx0), mn1 = fmaxf(m1, mx1);
            float a0 = fast_ex2(m0 - mn0), a1 = fast_ex2(m1 - mn1);
            m0 = mn0; m1 = mn1;
            #pragma unroll
            for (int j = 0; j < 3; j++) {
                oacc[j][0] *= a0; oacc[j][1] *= a0;
                oacc[j][2] *= a1; oacc[j][3] *= a1;
            }
            #pragma unroll
            for (int ks = 0; ks < 4; ks++) {
                uint32_t pf[4];
                pf[0] = ex2_h2(pack_h2(sacc[2*ks][0]   - m0, sacc[2*ks][1]   - m0));
                pf[1] = ex2_h2(pack_h2(sacc[2*ks][2]   - m1, sacc[2*ks][3]   - m1));
                pf[2] = ex2_h2(pack_h2(sacc[2*ks+1][0] - m0, sacc[2*ks+1][1] - m0));
                pf[3] = ex2_h2(pack_h2(sacc[2*ks+1][2] - m1, sacc[2*ks+1][3] - m1));
                int kh = c * 32 + ks * 8;
                #pragma unroll
                for (int j = 0; j < 3; j++) {
                    uint32_t bf[2];
                    bf[0] = Vh[(kh + t) * VPH + j * 8 + g];
                    bf[1] = Vh[(kh + t + 4) * VPH + j * 8 + g];
                    mma16n8k16(oacc[j], pf, bf);
                }
            }
        }

        float l0 = __shfl_sync(0xffffffffu, oacc[2][0], lane & 28);
        float l1 = __shfl_sync(0xffffffffu, oacc[2][2], lane & 28);
        float inv0 = 1.f / l0, inv1 = 1.f / l1;

        #pragma unroll
        for (int half = 0; half < 2; half++) {
            int n = qb + g + 8 * half;
            int hq = n / WS, wq = n % WS;
            float inv = half ? inv1 : inv0;
            int l = tok_to_l(n, br, wn);
            uint32_t* orow = g_atth + (size_t)(b * L_DIM + l) * 64 + cw;
            #pragma unroll
            for (int j = 0; j < 2; j++) {
                int d0 = j * 8 + 2 * t;
                float lp0 = bsm[d0], lp1 = bsm[d0 + 1];
                #pragma unroll
                for (int ky = 0; ky < 3; ky++) {
                    int hh = hq + ky - 1;
                    if (hh < 0 || hh >= HS) continue;
                    #pragma unroll
                    for (int kx = 0; kx < 3; kx++) {
                        int ww = wq + kx - 1;
                        if (ww < 0 || ww >= WS) continue;
                        uint32_t u = Qh[(j * 4 + t) * QP + hh * WS + ww];
                        float2 qf = __half22float2(*(__half2*)&u);
                        lp0 = fmaf(wsm[d0 * 9 + ky * 3 + kx], qf.x, lp0);
                        lp1 = fmaf(wsm[(d0 + 1) * 9 + ky * 3 + kx], qf.y, lp1);
                    }
                }
                float v0 = oacc[j][2 * half]     * inv + lp0;
                float v1 = oacc[j][2 * half + 1] * inv + lp1;
                orow[d0 >> 1] = pack_h2(v0, v1);
            }
        }
    }
}

// ---------------------------------------------------------------------------
extern "C" void kernel_launch(void* const* d_in, const int* in_sizes, int n_in,
                              void* d_out, int out_size) {
    const float* x       = (const float*)d_in[0];
    const float* z       = (const float*)d_in[1];
    const float* ln1_g   = (const float*)d_in[2];
    const float* ln1_b   = (const float*)d_in[3];
    const float* ln2_g   = (const float*)d_in[4];
    const float* ln2_b   = (const float*)d_in[5];
    const float* Wz1     = (const float*)d_in[6];
    const float* Wz2     = (const float*)d_in[7];
    const float* Wqkv    = (const float*)d_in[8];
    const float* Wproj   = (const float*)d_in[9];
    const float* bproj   = (const float*)d_in[10];
    const float* lepe_w0 = (const float*)d_in[11];
    const float* lepe_b0 = (const float*)d_in[12];
    const float* lepe_w1 = (const float*)d_in[13];
    const float* lepe_b1 = (const float*)d_in[14];
    const float* W1      = (const float*)d_in[15];
    const float* b1      = (const float*)d_in[16];
    const float* W2      = (const float*)d_in[17];
    const float* b2      = (const float*)d_in[18];
    float* out = (float*)d_out;

    float*    p_xf;    cudaGetSymbolAddress((void**)&p_xf,    g_xf);
    float*    p_xf2;   cudaGetSymbolAddress((void**)&p_xf2,   g_xf2);
    uint32_t* p_h1h;   cudaGetSymbolAddress((void**)&p_h1h,   g_h1h);
    uint32_t* p_qkvh;  cudaGetSymbolAddress((void**)&p_qkvh,  g_qkvh);
    uint32_t* p_atth;  cudaGetSymbolAddress((void**)&p_atth,  g_atth);
    uint32_t* p_h2h;   cudaGetSymbolAddress((void**)&p_h2h,   g_h2h);
    uint32_t* p_midh;  cudaGetSymbolAddress((void**)&p_midh,  g_midh);
    uint32_t* p_wqkvh; cudaGetSymbolAddress((void**)&p_wqkvh, g_wqkvh);
    uint32_t* p_wprojh;cudaGetSymbolAddress((void**)&p_wprojh,g_wprojh);
    uint32_t* p_w1h;   cudaGetSymbolAddress((void**)&p_w1h,   g_w1h);
    uint32_t* p_w2h;   cudaGetSymbolAddress((void**)&p_w2h,   g_w2h);

    const int attn_smem = ATTN_SMEM_WORDS * (int)sizeof(uint32_t);
    cudaFuncSetAttribute(attn_kernel, cudaFuncAttributeMaxDynamicSharedMemorySize, attn_smem);

    // 1) z projections + weight fp16 conversion
    prep_kernel<<<56, 256>>>(z, Wz1, Wz2, Wqkv, Wproj, W1, W2);
    // 2) transpose + LN1 (+z1): xf fp32, h1 fp16
    ln1_kernel<<<dim3(128, 8), 256>>>(x, ln1_g, ln1_b);
    // 3) qkv = h1 @ Wqkv^T  -> fp16, Q pre-scaled
    gemm_h<1><<<dim3(QKV_N / 128, M_ROWS / 128), 256>>>(
        p_h1h, p_wqkvh, nullptr, nullptr, p_qkvh, M_ROWS, QKV_N, C_DIM, 0, 1);
    // 4) windowed attention + LePE -> att fp16
    attn_kernel<<<dim3(64, 4, 2), 256, attn_smem>>>(lepe_w0, lepe_b0, lepe_w1, lepe_b1);
    // 5) xf2 = xf + att @ Wproj^T + bproj (fp32);  h2 = LN2(xf2)+z2 (fp16)
    gemm_ln_kernel<<<dim3(1, M_ROWS / 128), 256>>>(
        p_atth, p_wprojh, bproj, p_xf, p_xf2, p_h2h, ln2_g, ln2_b, M_ROWS, C_DIM);
    // 6) mid = gelu(h2 @ W1^T + b1) -> fp16
    gemm_h<1><<<dim3(HID / 128, M_ROWS / 128), 256>>>(
        p_h2h, p_w1h, b1, nullptr, p_midh, M_ROWS, HID, C_DIM, 1, 0);
    // 7) out = T(xf2 + mid @ W2^T + b2)  -> (B,C,H,W), fused transpose
    gemm_trans_kernel<<<dim3(1, M_ROWS / 128), 256>>>(
        p_midh, p_w2h, b2, p_xf2, out, M_ROWS, HID);
}